// round 1
// baseline (speedup 1.0000x reference)
#include <cuda_runtime.h>
#include <math.h>

// Problem constants (shapes fixed by the dataset; actual M/E read from in_sizes)
#define NMAX 50048
#define DH 128
typedef unsigned long long u64;

// Scratch: z, rh, y, w, agg  (5 x N x 128 fp32) + counts
__device__ float g_scratch[(size_t)NMAX * DH * 5];
__device__ int g_cnt[NMAX];

__device__ __forceinline__ u64 pack2(float lo, float hi) {
    u64 r; asm("mov.b64 %0, {%1, %2};" : "=l"(r) : "f"(lo), "f"(hi)); return r;
}
__device__ __forceinline__ void unpack2(u64 v, float& lo, float& hi) {
    asm("mov.b64 {%0, %1}, %2;" : "=f"(lo), "=f"(hi) : "l"(v));
}
__device__ __forceinline__ void fma2(u64& acc, u64 a, u64 b) {
    asm("fma.rn.f32x2 %0, %1, %2, %0;" : "+l"(acc) : "l"(a), "l"(b));
}
__device__ __forceinline__ float sgm(float x) { return 1.f / (1.f + __expf(-x)); }

// C[M,128] = A1[M,128]@B1[128,128] + A2[M,128]@B2[128,128], fused epilogue.
// EPI 0: C = acc
// EPI 1: C = sigmoid(acc + bias)            (update gate z)
// EPI 2: C = sigmoid(acc + bias) * H        (r * h_prev)
template <int EPI>
__global__ void __launch_bounds__(256) gemm_dual(
    const float* __restrict__ A1, const float* __restrict__ A2,
    const float* __restrict__ B1, const float* __restrict__ B2,
    const float* __restrict__ bias, const float* __restrict__ H,
    float* __restrict__ C, int M)
{
    __shared__ float As[16][132];   // [k][m], padded
    __shared__ float Bs[16][132];   // [k][n], padded (132*4 % 16 == 0 -> float4 ok)

    const int t = threadIdx.x;
    const int tx = t & 15;          // n-dim: cols tx*8 .. tx*8+7
    const int ty = t >> 4;          // m-dim: rows ty*8 .. ty*8+7
    const int m0 = blockIdx.x * 128;

    u64 acc[8][4];                  // 8 rows x 4 f32x2-pairs (8 cols)
    #pragma unroll
    for (int i = 0; i < 8; ++i)
        #pragma unroll
        for (int j = 0; j < 4; ++j) acc[i][j] = 0ull;

    #pragma unroll
    for (int half = 0; half < 2; ++half) {
        const float* A = half ? A2 : A1;
        const float* B = half ? B2 : B1;
        for (int k0 = 0; k0 < 128; k0 += 16) {
            // Load A chunk [128 rows x 16 k], store transposed As[k][m]
            #pragma unroll
            for (int l = 0; l < 2; ++l) {
                int i = t + l * 256;            // 0..511
                int row = i >> 2, kq = i & 3;
                float4 v = make_float4(0.f, 0.f, 0.f, 0.f);
                if (m0 + row < M)
                    v = *(const float4*)(A + (size_t)(m0 + row) * 128 + k0 + kq * 4);
                As[kq * 4 + 0][row] = v.x;
                As[kq * 4 + 1][row] = v.y;
                As[kq * 4 + 2][row] = v.z;
                As[kq * 4 + 3][row] = v.w;
            }
            // Load B chunk [16 k x 128 n]
            #pragma unroll
            for (int l = 0; l < 2; ++l) {
                int i = t + l * 256;
                int r = i >> 5, c = i & 31;
                *(float4*)&Bs[r][c * 4] =
                    *(const float4*)(B + (size_t)(k0 + r) * 128 + c * 4);
            }
            __syncthreads();
            #pragma unroll
            for (int kk = 0; kk < 16; ++kk) {
                float4 a0 = *(const float4*)&As[kk][ty * 8];
                float4 a1 = *(const float4*)&As[kk][ty * 8 + 4];
                float4 b0 = *(const float4*)&Bs[kk][tx * 8];
                float4 b1 = *(const float4*)&Bs[kk][tx * 8 + 4];
                u64 b2[4];
                b2[0] = pack2(b0.x, b0.y); b2[1] = pack2(b0.z, b0.w);
                b2[2] = pack2(b1.x, b1.y); b2[3] = pack2(b1.z, b1.w);
                float av[8] = {a0.x, a0.y, a0.z, a0.w, a1.x, a1.y, a1.z, a1.w};
                #pragma unroll
                for (int i = 0; i < 8; ++i) {
                    u64 a2 = pack2(av[i], av[i]);
                    #pragma unroll
                    for (int j = 0; j < 4; ++j) fma2(acc[i][j], a2, b2[j]);
                }
            }
            __syncthreads();
        }
    }

    float bv[8];
    if (EPI != 0) {
        #pragma unroll
        for (int j = 0; j < 8; ++j) bv[j] = bias[tx * 8 + j];
    }
    #pragma unroll
    for (int i = 0; i < 8; ++i) {
        int row = m0 + ty * 8 + i;
        if (row < M) {
            float v[8];
            #pragma unroll
            for (int j = 0; j < 4; ++j) unpack2(acc[i][j], v[2 * j], v[2 * j + 1]);
            if (EPI == 1) {
                #pragma unroll
                for (int j = 0; j < 8; ++j) v[j] = sgm(v[j] + bv[j]);
            } else if (EPI == 2) {
                const float4* hp = (const float4*)(H + (size_t)row * 128 + tx * 8);
                float4 h0 = hp[0], h1 = hp[1];
                float hh[8] = {h0.x, h0.y, h0.z, h0.w, h1.x, h1.y, h1.z, h1.w};
                #pragma unroll
                for (int j = 0; j < 8; ++j) v[j] = sgm(v[j] + bv[j]) * hh[j];
            }
            float4* cp = (float4*)(C + (size_t)row * 128 + tx * 8);
            cp[0] = make_float4(v[0], v[1], v[2], v[3]);
            cp[1] = make_float4(v[4], v[5], v[6], v[7]);
        }
    }
}

// One warp per edge: RED-add y[src] (128 floats) into agg[dst], count edges per dst.
__global__ void __launch_bounds__(256) scatter_kernel(
    const int* __restrict__ ei, const float* __restrict__ y,
    float* __restrict__ agg, int* __restrict__ cnt, int E)
{
    int gw = (int)((blockIdx.x * 256u + threadIdx.x) >> 5);
    int lane = threadIdx.x & 31;
    if (gw >= E) return;
    int src = __ldg(ei + gw);
    int dst = __ldg(ei + E + gw);
    float4 v = *(const float4*)(y + (size_t)src * 128 + lane * 4);
    float* a = agg + (size_t)dst * 128 + lane * 4;
    atomicAdd(a + 0, v.x);
    atomicAdd(a + 1, v.y);
    atomicAdd(a + 2, v.z);
    atomicAdd(a + 3, v.w);
    if (lane == 0) atomicAdd(cnt + dst, 1);
}

// out = (1-z) * (agg/max(cnt,1) + b_l + w) + z * h
__global__ void __launch_bounds__(256) final_kernel(
    const float* __restrict__ z, const float* __restrict__ w,
    const float* __restrict__ agg, const int* __restrict__ cnt,
    const float* __restrict__ b_l, const float* __restrict__ h,
    float* __restrict__ out, int M)
{
    int i4 = blockIdx.x * 256 + threadIdx.x;
    if (i4 >= M * 32) return;
    int node = i4 >> 5;
    int c4 = i4 & 31;
    float inv = 1.f / fmaxf((float)__ldg(cnt + node), 1.f);
    size_t off = (size_t)i4 * 4;
    float4 zv = *(const float4*)(z + off);
    float4 wv = *(const float4*)(w + off);
    float4 av = *(const float4*)(agg + off);
    float4 hv = *(const float4*)(h + off);
    float4 bv = *(const float4*)(b_l + c4 * 4);
    float4 o;
    o.x = (1.f - zv.x) * (av.x * inv + bv.x + wv.x) + zv.x * hv.x;
    o.y = (1.f - zv.y) * (av.y * inv + bv.y + wv.y) + zv.y * hv.y;
    o.z = (1.f - zv.z) * (av.z * inv + bv.z + wv.z) + zv.z * hv.z;
    o.w = (1.f - zv.w) * (av.w * inv + bv.w + wv.w) + zv.w * hv.w;
    *(float4*)(out + off) = o;
}

extern "C" void kernel_launch(void* const* d_in, const int* in_sizes, int n_in,
                              void* d_out, int out_size)
{
    const float* x    = (const float*)d_in[0];
    const int*   ei   = (const int*)d_in[1];
    const float* h    = (const float*)d_in[2];
    const float* W_xr = (const float*)d_in[3];
    const float* b_xr = (const float*)d_in[4];
    const float* W_hr = (const float*)d_in[5];
    const float* W_xz = (const float*)d_in[6];
    const float* b_xz = (const float*)d_in[7];
    const float* W_hz = (const float*)d_in[8];
    const float* W_l  = (const float*)d_in[9];
    const float* b_l  = (const float*)d_in[10];
    const float* W_r  = (const float*)d_in[11];
    float* out = (float*)d_out;

    const int M = in_sizes[0] / 128;   // nodes
    const int E = in_sizes[1] / 2;     // edges
    const size_t ND = (size_t)M * 128;

    void* ps = nullptr; cudaGetSymbolAddress(&ps, g_scratch);
    void* pc = nullptr; cudaGetSymbolAddress(&pc, g_cnt);
    float* z   = (float*)ps;
    float* rh  = z  + ND;
    float* y   = rh + ND;
    float* w   = y  + ND;
    float* agg = w  + ND;
    int*   cnt = (int*)pc;

    cudaMemsetAsync(agg, 0, ND * sizeof(float), 0);
    cudaMemsetAsync(cnt, 0, M * sizeof(int), 0);

    int gb = (M + 127) / 128;
    // z = sigmoid(x@W_xz + h@W_hz + b_xz)
    gemm_dual<1><<<gb, 256>>>(x, h, W_xz, W_hz, b_xz, nullptr, z, M);
    // rh = sigmoid(x@W_xr + h@W_hr + b_xr) * h
    gemm_dual<2><<<gb, 256>>>(x, h, W_xr, W_hr, b_xr, h, rh, M);
    // y = x@W_l[:128] + rh@W_l[128:]   (projected neighbor message)
    gemm_dual<0><<<gb, 256>>>(x, rh, W_l, W_l + 128 * 128, nullptr, nullptr, y, M);
    // w = x@W_r[:128] + rh@W_r[128:]   (root term)
    gemm_dual<0><<<gb, 256>>>(x, rh, W_r, W_r + 128 * 128, nullptr, nullptr, w, M);

    scatter_kernel<<<(E + 7) / 8, 256>>>(ei, y, agg, cnt, E);

    final_kernel<<<(M * 32 + 255) / 256, 256>>>(z, w, agg, cnt, b_l, h, out, M);
}

// round 2
// speedup vs baseline: 1.6196x; 1.6196x over previous
#include <cuda_runtime.h>
#include <math.h>

#define NMAX 50048
#define DH 128
typedef unsigned long long u64;

// Scratch: z, rh, y, w, agg  (5 x N x 128 fp32) + counts
__device__ float g_scratch[(size_t)NMAX * DH * 5];
__device__ int g_cnt[NMAX];

__device__ __forceinline__ u64 pack2(float lo, float hi) {
    u64 r; asm("mov.b64 %0, {%1, %2};" : "=l"(r) : "f"(lo), "f"(hi)); return r;
}
__device__ __forceinline__ void unpack2(u64 v, float& lo, float& hi) {
    asm("mov.b64 {%0, %1}, %2;" : "=f"(lo), "=f"(hi) : "l"(v));
}
__device__ __forceinline__ void fma2(u64& acc, u64 a, u64 b) {
    asm("fma.rn.f32x2 %0, %1, %2, %0;" : "+l"(acc) : "l"(a), "l"(b));
}
__device__ __forceinline__ float sgm(float x) { return 1.f / (1.f + __expf(-x)); }

// C[M,128] = A1[M,128]@B1[128,128] + A2[M,128]@B2[128,128], fused epilogue.
// EPI 0: C = acc ; EPI 1: C = sigmoid(acc+bias) ; EPI 2: C = sigmoid(acc+bias)*H
//
// SMEM layouts are pre-packed for fma.rn.f32x2:
//   As4[k][p2][ty] : uint4 = rows (8ty+4p2 .. +3) of column k  -> two row-pair u64s
//   Bs4[k][j2][tx] : uint4 = cols (tx*8+2j2, tx*8+2j2+1), each DUPLICATED as {b,b}
// Inner loop per k: 2+4 LDS.128 + 32 fma2, no packing movs.
template <int EPI>
__global__ void __launch_bounds__(256) gemm_dual(
    const float* __restrict__ A1, const float* __restrict__ A2,
    const float* __restrict__ B1, const float* __restrict__ B2,
    const float* __restrict__ bias, const float* __restrict__ H,
    float* __restrict__ C, int M)
{
    __shared__ uint4 As4[16][2][17];   // 8704 B (pad 17 vs 16)
    __shared__ uint4 Bs4[16][4][17];   // 17408 B

    const int t  = threadIdx.x;
    const int tx = t & 15;             // n-dim: cols tx*8 .. +7
    const int ty = t >> 4;             // m-dim: rows ty*8 .. +7
    const int m0 = blockIdx.x * 128;

    u64 acc[4][8];                     // [row-pair p][col c]
    #pragma unroll
    for (int p = 0; p < 4; ++p)
        #pragma unroll
        for (int c = 0; c < 8; ++c) acc[p][c] = 0ull;

    #pragma unroll
    for (int half = 0; half < 2; ++half) {
        const float* A = half ? A2 : A1;
        const float* B = half ? B2 : B1;
        for (int k0 = 0; k0 < 128; k0 += 16) {
            // ---- stage A chunk [128 rows x 16 k] into pair-packed As4 ----
            #pragma unroll
            for (int l = 0; l < 2; ++l) {
                int i = t + l * 256;            // 0..511
                int row = i >> 2, kq = i & 3;   // 4 k-values per float4
                float4 v = make_float4(0.f, 0.f, 0.f, 0.f);
                if (m0 + row < M)
                    v = *(const float4*)(A + (size_t)(m0 + row) * 128 + k0 + kq * 4);
                int tty = row >> 3, p2 = (row >> 2) & 1, w = row & 3;
                float* base;
                base = (float*)&As4[kq * 4 + 0][p2][tty]; base[w] = v.x;
                base = (float*)&As4[kq * 4 + 1][p2][tty]; base[w] = v.y;
                base = (float*)&As4[kq * 4 + 2][p2][tty]; base[w] = v.z;
                base = (float*)&As4[kq * 4 + 3][p2][tty]; base[w] = v.w;
            }
            // ---- stage B chunk [16 k x 128 n] into duplicated Bs4 ----
            #pragma unroll
            for (int l = 0; l < 2; ++l) {
                int i = t + l * 256;            // 0..511
                int r = i >> 5, c = i & 31;     // k-row r, float4 col-group c
                float4 v = *(const float4*)(B + (size_t)(k0 + r) * 128 + c * 4);
                float vv[4] = {v.x, v.y, v.z, v.w};
                #pragma unroll
                for (int q = 0; q < 4; ++q) {
                    int n = c * 4 + q;
                    int ttx = n >> 3, j = n & 7;
                    ((u64*)&Bs4[r][j >> 1][ttx])[j & 1] = pack2(vv[q], vv[q]);
                }
            }
            __syncthreads();
            #pragma unroll
            for (int kk = 0; kk < 16; ++kk) {
                uint4 a0 = As4[kk][0][ty];
                uint4 a1 = As4[kk][1][ty];
                uint4 b0 = Bs4[kk][0][tx];
                uint4 b1 = Bs4[kk][1][tx];
                uint4 b2 = Bs4[kk][2][tx];
                uint4 b3 = Bs4[kk][3][tx];
                u64 ap[4]; u64 bq[8];
                ap[0] = ((u64*)&a0)[0]; ap[1] = ((u64*)&a0)[1];
                ap[2] = ((u64*)&a1)[0]; ap[3] = ((u64*)&a1)[1];
                bq[0] = ((u64*)&b0)[0]; bq[1] = ((u64*)&b0)[1];
                bq[2] = ((u64*)&b1)[0]; bq[3] = ((u64*)&b1)[1];
                bq[4] = ((u64*)&b2)[0]; bq[5] = ((u64*)&b2)[1];
                bq[6] = ((u64*)&b3)[0]; bq[7] = ((u64*)&b3)[1];
                #pragma unroll
                for (int p = 0; p < 4; ++p)
                    #pragma unroll
                    for (int c = 0; c < 8; ++c) fma2(acc[p][c], ap[p], bq[c]);
            }
            __syncthreads();
        }
    }

    float bv[8];
    if (EPI != 0) {
        #pragma unroll
        for (int j = 0; j < 8; ++j) bv[j] = bias[tx * 8 + j];
    }
    #pragma unroll
    for (int p = 0; p < 4; ++p) {
        #pragma unroll
        for (int s = 0; s < 2; ++s) {               // lo/hi of the pair
            int row = m0 + ty * 8 + 2 * p + s;
            if (row < M) {
                float v[8];
                #pragma unroll
                for (int c = 0; c < 8; ++c) {
                    float lo, hi; unpack2(acc[p][c], lo, hi);
                    v[c] = s ? hi : lo;
                }
                if (EPI == 1) {
                    #pragma unroll
                    for (int j = 0; j < 8; ++j) v[j] = sgm(v[j] + bv[j]);
                } else if (EPI == 2) {
                    const float4* hp = (const float4*)(H + (size_t)row * 128 + tx * 8);
                    float4 h0 = hp[0], h1 = hp[1];
                    float hh[8] = {h0.x, h0.y, h0.z, h0.w, h1.x, h1.y, h1.z, h1.w};
                    #pragma unroll
                    for (int j = 0; j < 8; ++j) v[j] = sgm(v[j] + bv[j]) * hh[j];
                }
                float4* cp = (float4*)(C + (size_t)row * 128 + tx * 8);
                cp[0] = make_float4(v[0], v[1], v[2], v[3]);
                cp[1] = make_float4(v[4], v[5], v[6], v[7]);
            }
        }
    }
}

// One warp per edge: vectorized RED (v4.f32) of y[src] into agg[dst] — 4x fewer
// L2 atomic ops than scalar atomicAdd (the round-1 bottleneck).
__global__ void __launch_bounds__(256) scatter_kernel(
    const int* __restrict__ ei, const float* __restrict__ y,
    float* __restrict__ agg, int* __restrict__ cnt, int E)
{
    int gw = (int)((blockIdx.x * 256u + threadIdx.x) >> 5);
    int lane = threadIdx.x & 31;
    if (gw >= E) return;
    int src = __ldg(ei + gw);
    int dst = __ldg(ei + E + gw);
    float4 v = *(const float4*)(y + (size_t)src * 128 + lane * 4);
    float* a = agg + (size_t)dst * 128 + lane * 4;
    asm volatile("red.global.add.v4.f32 [%0], {%1, %2, %3, %4};"
                 :: "l"(a), "f"(v.x), "f"(v.y), "f"(v.z), "f"(v.w) : "memory");
    if (lane == 0) atomicAdd(cnt + dst, 1);
}

// out = (1-z) * (agg/max(cnt,1) + b_l + w) + z * h
__global__ void __launch_bounds__(256) final_kernel(
    const float* __restrict__ z, const float* __restrict__ w,
    const float* __restrict__ agg, const int* __restrict__ cnt,
    const float* __restrict__ b_l, const float* __restrict__ h,
    float* __restrict__ out, int M)
{
    int i4 = blockIdx.x * 256 + threadIdx.x;
    if (i4 >= M * 32) return;
    int node = i4 >> 5;
    int c4 = i4 & 31;
    float inv = 1.f / fmaxf((float)__ldg(cnt + node), 1.f);
    size_t off = (size_t)i4 * 4;
    float4 zv = *(const float4*)(z + off);
    float4 wv = *(const float4*)(w + off);
    float4 av = *(const float4*)(agg + off);
    float4 hv = *(const float4*)(h + off);
    float4 bv = *(const float4*)(b_l + c4 * 4);
    float4 o;
    o.x = (1.f - zv.x) * (av.x * inv + bv.x + wv.x) + zv.x * hv.x;
    o.y = (1.f - zv.y) * (av.y * inv + bv.y + wv.y) + zv.y * hv.y;
    o.z = (1.f - zv.z) * (av.z * inv + bv.z + wv.z) + zv.z * hv.z;
    o.w = (1.f - zv.w) * (av.w * inv + bv.w + wv.w) + zv.w * hv.w;
    *(float4*)(out + off) = o;
}

extern "C" void kernel_launch(void* const* d_in, const int* in_sizes, int n_in,
                              void* d_out, int out_size)
{
    const float* x    = (const float*)d_in[0];
    const int*   ei   = (const int*)d_in[1];
    const float* h    = (const float*)d_in[2];
    const float* W_xr = (const float*)d_in[3];
    const float* b_xr = (const float*)d_in[4];
    const float* W_hr = (const float*)d_in[5];
    const float* W_xz = (const float*)d_in[6];
    const float* b_xz = (const float*)d_in[7];
    const float* W_hz = (const float*)d_in[8];
    const float* W_l  = (const float*)d_in[9];
    const float* b_l  = (const float*)d_in[10];
    const float* W_r  = (const float*)d_in[11];
    float* out = (float*)d_out;

    const int M = in_sizes[0] / 128;   // nodes
    const int E = in_sizes[1] / 2;     // edges
    const size_t ND = (size_t)M * 128;

    void* ps = nullptr; cudaGetSymbolAddress(&ps, g_scratch);
    void* pc = nullptr; cudaGetSymbolAddress(&pc, g_cnt);
    float* z   = (float*)ps;
    float* rh  = z  + ND;
    float* y   = rh + ND;
    float* w   = y  + ND;
    float* agg = w  + ND;
    int*   cnt = (int*)pc;

    cudaMemsetAsync(agg, 0, ND * sizeof(float), 0);
    cudaMemsetAsync(cnt, 0, M * sizeof(int), 0);

    int gb = (M + 127) / 128;
    // z = sigmoid(x@W_xz + h@W_hz + b_xz)
    gemm_dual<1><<<gb, 256>>>(x, h, W_xz, W_hz, b_xz, nullptr, z, M);
    // rh = sigmoid(x@W_xr + h@W_hr + b_xr) * h
    gemm_dual<2><<<gb, 256>>>(x, h, W_xr, W_hr, b_xr, h, rh, M);
    // y = x@W_l[:128] + rh@W_l[128:]   (projected neighbor message)
    gemm_dual<0><<<gb, 256>>>(x, rh, W_l, W_l + 128 * 128, nullptr, nullptr, y, M);
    // w = x@W_r[:128] + rh@W_r[128:]   (root term)
    gemm_dual<0><<<gb, 256>>>(x, rh, W_r, W_r + 128 * 128, nullptr, nullptr, w, M);

    scatter_kernel<<<(E + 7) / 8, 256>>>(ei, y, agg, cnt, E);

    final_kernel<<<(M * 32 + 255) / 256, 256>>>(z, w, agg, cnt, b_l, h, out, M);
}

// round 4
// speedup vs baseline: 2.7057x; 1.6706x over previous
#include <cuda_runtime.h>
#include <cuda_bf16.h>
#include <math.h>
#include <stdint.h>

#define NMAX 50048
typedef unsigned long long u64;

// Scratch: z, rh, y, w, agg (5 x N x 128 fp32) + counts + prepped weights
__device__ float g_scratch[(size_t)NMAX * 128 * 5];
__device__ int g_cnt[NMAX];
// 4 matrices x {hi,lo} x [128 n][256 k] bf16
__device__ __nv_bfloat16 g_wbuf[8 * 128 * 256];

__device__ __forceinline__ float sgm(float x) { return 1.f / (1.f + __expf(-x)); }

__device__ __forceinline__ uint32_t smem_u32(const void* p) {
    uint32_t a;
    asm("{ .reg .u64 t; cvta.to.shared.u64 t, %1; cvt.u32.u64 %0, t; }" : "=r"(a) : "l"(p));
    return a;
}
__device__ __forceinline__ void ldmx4(uint32_t* r, uint32_t addr) {
    asm volatile("ldmatrix.sync.aligned.m8n8.x4.shared.b16 {%0,%1,%2,%3}, [%4];"
                 : "=r"(r[0]), "=r"(r[1]), "=r"(r[2]), "=r"(r[3]) : "r"(addr));
}
__device__ __forceinline__ void ldmx2(uint32_t* r, uint32_t addr) {
    asm volatile("ldmatrix.sync.aligned.m8n8.x2.shared.b16 {%0,%1}, [%2];"
                 : "=r"(r[0]), "=r"(r[1]) : "r"(addr));
}
__device__ __forceinline__ void mma16816(float* c, const uint32_t* a, const uint32_t* b) {
    asm volatile(
        "mma.sync.aligned.m16n8k16.row.col.f32.bf16.bf16.f32 "
        "{%0,%1,%2,%3}, {%4,%5,%6,%7}, {%8,%9}, {%0,%1,%2,%3};"
        : "+f"(c[0]), "+f"(c[1]), "+f"(c[2]), "+f"(c[3])
        : "r"(a[0]), "r"(a[1]), "r"(a[2]), "r"(a[3]), "r"(b[0]), "r"(b[1]));
}
__device__ __forceinline__ uint32_t packbf2(float a, float b) {
    __nv_bfloat162 p = __halves2bfloat162(__float2bfloat16_rn(a), __float2bfloat16_rn(b));
    return *(uint32_t*)&p;
}

// ---------------------------------------------------------------------------
// Weight prep: 4 logical [256,128] fp32 matrices -> transposed [128 n][256 k]
// bf16 hi/lo split. mat 0: (W_xz|W_hz)  1: (W_xr|W_hr)  2: W_l  3: W_r(sage)
// ---------------------------------------------------------------------------
__global__ void __launch_bounds__(256) prep_w(
    const float* __restrict__ W0x, const float* __restrict__ W0h,
    const float* __restrict__ W1x, const float* __restrict__ W1h,
    const float* __restrict__ W2, const float* __restrict__ W3,
    __nv_bfloat16* __restrict__ wbuf)
{
    int i = blockIdx.x * 256 + threadIdx.x;   // 4 * 32768
    int mat = i >> 15;
    int r = i & 32767;
    int n = r >> 8, k = r & 255;
    const float *Wx, *Wh;
    if (mat == 0)      { Wx = W0x; Wh = W0h; }
    else if (mat == 1) { Wx = W1x; Wh = W1h; }
    else if (mat == 2) { Wx = W2;  Wh = W2 + 16384; }
    else               { Wx = W3;  Wh = W3 + 16384; }
    float w = (k < 128) ? Wx[(size_t)k * 128 + n] : Wh[(size_t)(k - 128) * 128 + n];
    __nv_bfloat16 hi = __float2bfloat16_rn(w);
    __nv_bfloat16 lo = __float2bfloat16_rn(w - __bfloat162float(hi));
    wbuf[(size_t)(2 * mat) * 32768 + n * 256 + k] = hi;
    wbuf[(size_t)(2 * mat + 1) * 32768 + n * 256 + k] = lo;
}

// ---------------------------------------------------------------------------
// HMMA GEMM: C[M,128] = [A1|A2][M,256] @ W[256,128].
// mma.sync m16n8k16 bf16, 3-term split (AhBh + AhBl + AlBh), fp32 accum.
// CTA: 128x128 tile, 8 warps (4x2), warp tile 32x64.
// SMEM rows have 80-byte stride => conflict-free ldmatrix (granules distinct).
// EPI 0: C=acc ; 1: C=sigmoid(acc+bias) ; 2: C=sigmoid(acc+bias)*H
// ---------------------------------------------------------------------------
#define ROWB 80
template <int EPI>
__global__ void __launch_bounds__(256) gemm_mma(
    const float* __restrict__ A1, const float* __restrict__ A2,
    const __nv_bfloat16* __restrict__ Bhi, const __nv_bfloat16* __restrict__ Blo,
    const float* __restrict__ bias, const float* __restrict__ H,
    float* __restrict__ C, int M)
{
    __shared__ __align__(16) char sAh[128 * ROWB];
    __shared__ __align__(16) char sAl[128 * ROWB];
    __shared__ __align__(16) char sBh[128 * ROWB];
    __shared__ __align__(16) char sBl[128 * ROWB];

    const int t = threadIdx.x;
    const int wid = t >> 5, lane = t & 31;
    const int wm = wid >> 1, wn = wid & 1;      // warp grid 4x2
    const int m0 = blockIdx.x * 128;

    const uint32_t uAh = smem_u32(sAh), uAl = smem_u32(sAl);
    const uint32_t uBh = smem_u32(sBh), uBl = smem_u32(sBl);

    float acc[2][8][4];
    #pragma unroll
    for (int mt = 0; mt < 2; ++mt)
        #pragma unroll
        for (int nt = 0; nt < 8; ++nt)
            #pragma unroll
            for (int q = 0; q < 4; ++q) acc[mt][nt][q] = 0.f;

    const int srow = t >> 1;         // staging row 0..127
    const int shalf = t & 1;         // k 0..15 or 16..31 within chunk
    const bool valid = (m0 + srow) < M;

    for (int c = 0; c < 8; ++c) {    // 8 chunks of K=32 over total 256
        if (c > 0) __syncthreads();

        // ---- stage A: 16 fp32 -> 16 bf16 hi + 16 lo ----
        {
            const float* Asrc = (c < 4) ? A1 : A2;
            const float4* ap = (const float4*)(Asrc + (size_t)(m0 + srow) * 128
                                               + (c & 3) * 32 + shalf * 16);
            float f[16];
            #pragma unroll
            for (int j = 0; j < 4; ++j) {
                float4 v = valid ? ap[j] : make_float4(0.f, 0.f, 0.f, 0.f);
                f[4 * j] = v.x; f[4 * j + 1] = v.y; f[4 * j + 2] = v.z; f[4 * j + 3] = v.w;
            }
            uint32_t hw[8], lw[8];
            #pragma unroll
            for (int q = 0; q < 8; ++q) {
                float a = f[2 * q], b = f[2 * q + 1];
                float ah = __bfloat162float(__float2bfloat16_rn(a));
                float bh = __bfloat162float(__float2bfloat16_rn(b));
                hw[q] = packbf2(a, b);
                lw[q] = packbf2(a - ah, b - bh);
            }
            int off = srow * ROWB + shalf * 32;
            *(uint4*)(sAh + off)      = make_uint4(hw[0], hw[1], hw[2], hw[3]);
            *(uint4*)(sAh + off + 16) = make_uint4(hw[4], hw[5], hw[6], hw[7]);
            *(uint4*)(sAl + off)      = make_uint4(lw[0], lw[1], lw[2], lw[3]);
            *(uint4*)(sAl + off + 16) = make_uint4(lw[4], lw[5], lw[6], lw[7]);
        }
        // ---- stage B: copy prepped bf16 slice ----
        {
            const uint4* bh = (const uint4*)(Bhi + (size_t)srow * 256 + c * 32 + shalf * 16);
            const uint4* bl = (const uint4*)(Blo + (size_t)srow * 256 + c * 32 + shalf * 16);
            int off = srow * ROWB + shalf * 32;
            *(uint4*)(sBh + off)      = bh[0];
            *(uint4*)(sBh + off + 16) = bh[1];
            *(uint4*)(sBl + off)      = bl[0];
            *(uint4*)(sBl + off + 16) = bl[1];
        }
        __syncthreads();

        // ---- compute: 2 k-steps of 16 ----
        #pragma unroll
        for (int ks = 0; ks < 2; ++ks) {
            uint32_t ah[2][4], al[2][4];
            const int arow = wm * 32 + (lane & 15);
            const int akb = ks * 32 + (lane >> 4) * 16;
            #pragma unroll
            for (int mt = 0; mt < 2; ++mt) {
                uint32_t ao = (uint32_t)((arow + mt * 16) * ROWB + akb);
                ldmx4(ah[mt], uAh + ao);
                ldmx4(al[mt], uAl + ao);
            }
            const int brow = wn * 64 + (lane & 7);
            const int bkb = ks * 32 + ((lane >> 3) & 1) * 16;
            #pragma unroll
            for (int nt = 0; nt < 8; ++nt) {
                uint32_t bo = (uint32_t)((brow + nt * 8) * ROWB + bkb);
                uint32_t bh[2], bl[2];
                ldmx2(bh, uBh + bo);
                ldmx2(bl, uBl + bo);
                #pragma unroll
                for (int mt = 0; mt < 2; ++mt) {
                    mma16816(acc[mt][nt], ah[mt], bh);
                    mma16816(acc[mt][nt], ah[mt], bl);
                    mma16816(acc[mt][nt], al[mt], bh);
                }
            }
        }
    }

    // ---- epilogue ----
    const int g = lane >> 2, tig = lane & 3;
    #pragma unroll
    for (int mt = 0; mt < 2; ++mt) {
        #pragma unroll
        for (int nt = 0; nt < 8; ++nt) {
            int col = wn * 64 + nt * 8 + tig * 2;
            float bx = 0.f, by = 0.f;
            if (EPI != 0) { bx = __ldg(bias + col); by = __ldg(bias + col + 1); }
            #pragma unroll
            for (int s = 0; s < 2; ++s) {
                int r = m0 + wm * 32 + mt * 16 + g + s * 8;
                if (r < M) {
                    float v0 = acc[mt][nt][2 * s], v1 = acc[mt][nt][2 * s + 1];
                    if (EPI == 1) {
                        v0 = sgm(v0 + bx); v1 = sgm(v1 + by);
                    } else if (EPI == 2) {
                        const float2 hv = *(const float2*)(H + (size_t)r * 128 + col);
                        v0 = sgm(v0 + bx) * hv.x; v1 = sgm(v1 + by) * hv.y;
                    }
                    *(float2*)(C + (size_t)r * 128 + col) = make_float2(v0, v1);
                }
            }
        }
    }
}

// One warp per edge: vectorized RED (v4.f32) of y[src] into agg[dst].
__global__ void __launch_bounds__(256) scatter_kernel(
    const int* __restrict__ ei, const float* __restrict__ y,
    float* __restrict__ agg, int* __restrict__ cnt, int E)
{
    int gw = (int)((blockIdx.x * 256u + threadIdx.x) >> 5);
    int lane = threadIdx.x & 31;
    if (gw >= E) return;
    int src = __ldg(ei + gw);
    int dst = __ldg(ei + E + gw);
    float4 v = *(const float4*)(y + (size_t)src * 128 + lane * 4);
    float* a = agg + (size_t)dst * 128 + lane * 4;
    asm volatile("red.global.add.v4.f32 [%0], {%1, %2, %3, %4};"
                 :: "l"(a), "f"(v.x), "f"(v.y), "f"(v.z), "f"(v.w) : "memory");
    if (lane == 0) atomicAdd(cnt + dst, 1);
}

// out = (1-z) * (agg/max(cnt,1) + b_l + w) + z * h
__global__ void __launch_bounds__(256) final_kernel(
    const float* __restrict__ z, const float* __restrict__ w,
    const float* __restrict__ agg, const int* __restrict__ cnt,
    const float* __restrict__ b_l, const float* __restrict__ h,
    float* __restrict__ out, int M)
{
    int i4 = blockIdx.x * 256 + threadIdx.x;
    if (i4 >= M * 32) return;
    int node = i4 >> 5;
    int c4 = i4 & 31;
    float inv = 1.f / fmaxf((float)__ldg(cnt + node), 1.f);
    size_t off = (size_t)i4 * 4;
    float4 zv = *(const float4*)(z + off);
    float4 wv = *(const float4*)(w + off);
    float4 av = *(const float4*)(agg + off);
    float4 hv = *(const float4*)(h + off);
    float4 bv = *(const float4*)(b_l + c4 * 4);
    float4 o;
    o.x = (1.f - zv.x) * (av.x * inv + bv.x + wv.x) + zv.x * hv.x;
    o.y = (1.f - zv.y) * (av.y * inv + bv.y + wv.y) + zv.y * hv.y;
    o.z = (1.f - zv.z) * (av.z * inv + bv.z + wv.z) + zv.z * hv.z;
    o.w = (1.f - zv.w) * (av.w * inv + bv.w + wv.w) + zv.w * hv.w;
    *(float4*)(out + off) = o;
}

extern "C" void kernel_launch(void* const* d_in, const int* in_sizes, int n_in,
                              void* d_out, int out_size)
{
    const float* x    = (const float*)d_in[0];
    const int*   ei   = (const int*)d_in[1];
    const float* h    = (const float*)d_in[2];
    const float* W_xr = (const float*)d_in[3];
    const float* b_xr = (const float*)d_in[4];
    const float* W_hr = (const float*)d_in[5];
    const float* W_xz = (const float*)d_in[6];
    const float* b_xz = (const float*)d_in[7];
    const float* W_hz = (const float*)d_in[8];
    const float* W_l  = (const float*)d_in[9];
    const float* b_l  = (const float*)d_in[10];
    const float* W_r  = (const float*)d_in[11];
    float* out = (float*)d_out;

    const int M = in_sizes[0] / 128;
    const int E = in_sizes[1] / 2;
    const size_t ND = (size_t)M * 128;

    void* ps = nullptr; cudaGetSymbolAddress(&ps, g_scratch);
    void* pc = nullptr; cudaGetSymbolAddress(&pc, g_cnt);
    void* pw = nullptr; cudaGetSymbolAddress(&pw, g_wbuf);
    float* z   = (float*)ps;
    float* rh  = z  + ND;
    float* y   = rh + ND;
    float* w   = y  + ND;
    float* agg = w  + ND;
    int*   cnt = (int*)pc;
    __nv_bfloat16* wbuf = (__nv_bfloat16*)pw;

    cudaMemsetAsync(agg, 0, ND * sizeof(float), 0);
    cudaMemsetAsync(cnt, 0, M * sizeof(int), 0);

    // Prep weights: mat0=(W_xz|W_hz), mat1=(W_xr|W_hr), mat2=W_l, mat3=W_r
    prep_w<<<512, 256>>>(W_xz, W_hz, W_xr, W_hr, W_l, W_r, wbuf);

    __nv_bfloat16* BZ_hi = wbuf;
    __nv_bfloat16* BZ_lo = wbuf + 1 * 32768;
    __nv_bfloat16* BR_hi = wbuf + 2 * 32768;
    __nv_bfloat16* BR_lo = wbuf + 3 * 32768;
    __nv_bfloat16* BL_hi = wbuf + 4 * 32768;
    __nv_bfloat16* BL_lo = wbuf + 5 * 32768;
    __nv_bfloat16* BW_hi = wbuf + 6 * 32768;
    __nv_bfloat16* BW_lo = wbuf + 7 * 32768;

    int gb = (M + 127) / 128;
    // z = sigmoid([x|h] @ Wz + b_xz)
    gemm_mma<1><<<gb, 256>>>(x, h, BZ_hi, BZ_lo, b_xz, nullptr, z, M);
    // rh = sigmoid([x|h] @ Wr + b_xr) * h
    gemm_mma<2><<<gb, 256>>>(x, h, BR_hi, BR_lo, b_xr, h, rh, M);
    // y = [x|rh] @ W_l   (projected neighbor message)
    gemm_mma<0><<<gb, 256>>>(x, rh, BL_hi, BL_lo, nullptr, nullptr, y, M);
    // w = [x|rh] @ W_r   (root term)
    gemm_mma<0><<<gb, 256>>>(x, rh, BW_hi, BW_lo, nullptr, nullptr, w, M);

    scatter_kernel<<<(E + 7) / 8, 256>>>(ei, y, agg, cnt, E);

    final_kernel<<<(M * 32 + 255) / 256, 256>>>(z, w, agg, cnt, b_l, h, out, M);
}

// round 5
// speedup vs baseline: 3.0093x; 1.1122x over previous
#include <cuda_runtime.h>
#include <cuda_bf16.h>
#include <math.h>
#include <stdint.h>

#define NMAX 50048
typedef unsigned long long u64;

// Scratch: z, rh, y, w, agg (5 x N x 128 fp32) + counts + prepped weights
__device__ float g_scratch[(size_t)NMAX * 128 * 5];
__device__ int g_cnt[NMAX];
// 4 matrices x {hi,lo} x [128 n][256 k] bf16
__device__ __nv_bfloat16 g_wbuf[8 * 128 * 256];

__device__ __forceinline__ float sgm(float x) { return 1.f / (1.f + __expf(-x)); }

__device__ __forceinline__ uint32_t smem_u32(const void* p) {
    uint32_t a;
    asm("{ .reg .u64 t; cvta.to.shared.u64 t, %1; cvt.u32.u64 %0, t; }" : "=r"(a) : "l"(p));
    return a;
}
__device__ __forceinline__ void ldmx4(uint32_t* r, uint32_t addr) {
    asm volatile("ldmatrix.sync.aligned.m8n8.x4.shared.b16 {%0,%1,%2,%3}, [%4];"
                 : "=r"(r[0]), "=r"(r[1]), "=r"(r[2]), "=r"(r[3]) : "r"(addr));
}
__device__ __forceinline__ void ldmx2(uint32_t* r, uint32_t addr) {
    asm volatile("ldmatrix.sync.aligned.m8n8.x2.shared.b16 {%0,%1}, [%2];"
                 : "=r"(r[0]), "=r"(r[1]) : "r"(addr));
}
__device__ __forceinline__ void mma16816(float* c, const uint32_t* a, const uint32_t* b) {
    asm volatile(
        "mma.sync.aligned.m16n8k16.row.col.f32.bf16.bf16.f32 "
        "{%0,%1,%2,%3}, {%4,%5,%6,%7}, {%8,%9}, {%0,%1,%2,%3};"
        : "+f"(c[0]), "+f"(c[1]), "+f"(c[2]), "+f"(c[3])
        : "r"(a[0]), "r"(a[1]), "r"(a[2]), "r"(a[3]), "r"(b[0]), "r"(b[1]));
}
__device__ __forceinline__ uint32_t packbf2(float a, float b) {
    __nv_bfloat162 p = __halves2bfloat162(__float2bfloat16_rn(a), __float2bfloat16_rn(b));
    return *(uint32_t*)&p;
}
__device__ __forceinline__ void cpa16(uint32_t dst, const void* src) {
    asm volatile("cp.async.ca.shared.global [%0], [%1], 16;" :: "r"(dst), "l"(src) : "memory");
}
__device__ __forceinline__ void cp_commit() { asm volatile("cp.async.commit_group;" ::: "memory"); }
__device__ __forceinline__ void cp_wait0()  { asm volatile("cp.async.wait_group 0;" ::: "memory"); }

// ---------------------------------------------------------------------------
// Weight prep: 4 logical [256,128] fp32 matrices -> transposed [128 n][256 k]
// bf16 hi/lo split. mat 0: (W_xz|W_hz)  1: (W_xr|W_hr)  2: W_l  3: W_r(sage)
// ---------------------------------------------------------------------------
__global__ void __launch_bounds__(256) prep_w(
    const float* __restrict__ W0x, const float* __restrict__ W0h,
    const float* __restrict__ W1x, const float* __restrict__ W1h,
    const float* __restrict__ W2, const float* __restrict__ W3,
    __nv_bfloat16* __restrict__ wbuf)
{
    int i = blockIdx.x * 256 + threadIdx.x;   // 4 * 32768
    int mat = i >> 15;
    int r = i & 32767;
    int n = r >> 8, k = r & 255;
    const float *Wx, *Wh;
    if (mat == 0)      { Wx = W0x; Wh = W0h; }
    else if (mat == 1) { Wx = W1x; Wh = W1h; }
    else if (mat == 2) { Wx = W2;  Wh = W2 + 16384; }
    else               { Wx = W3;  Wh = W3 + 16384; }
    float w = (k < 128) ? Wx[(size_t)k * 128 + n] : Wh[(size_t)(k - 128) * 128 + n];
    __nv_bfloat16 hi = __float2bfloat16_rn(w);
    __nv_bfloat16 lo = __float2bfloat16_rn(w - __bfloat162float(hi));
    wbuf[(size_t)(2 * mat) * 32768 + n * 256 + k] = hi;
    wbuf[(size_t)(2 * mat + 1) * 32768 + n * 256 + k] = lo;
}

// ---------------------------------------------------------------------------
// Fused dual-B HMMA GEMM:
//   C0[M,128] = [A1|A2] @ W0,  C1[M,128] = [A1|A2] @ W1
// A staged/converted ONCE per chunk (registers->bf16 hi/lo SMEM, pipelined);
// B double-buffered via cp.async. 3-term bf16 split, fp32 accum.
// GATES=1: C0=sigmoid(acc0+bias0), C1=sigmoid(acc1+bias1)*H
// GATES=0: plain stores.
// SMEM rows 80B stride => conflict-free ldmatrix.
// ---------------------------------------------------------------------------
#define ROWB 80
#define TILEB (128 * ROWB)          // 10240 bytes per (matrix-part, buffer)
#define SB_OFF (2 * TILEB)          // after A hi/lo
#define SMEMSZ (SB_OFF + 8 * TILEB) // 102400 bytes

template <int GATES>
__global__ void __launch_bounds__(256, 1) gemm_dual2(
    const float* __restrict__ A1, const float* __restrict__ A2,
    const __nv_bfloat16* __restrict__ B0hi, const __nv_bfloat16* __restrict__ B0lo,
    const __nv_bfloat16* __restrict__ B1hi, const __nv_bfloat16* __restrict__ B1lo,
    const float* __restrict__ bias0, const float* __restrict__ bias1,
    const float* __restrict__ H,
    float* __restrict__ C0, float* __restrict__ C1, int M)
{
    extern __shared__ __align__(16) char smem[];
    const uint32_t sb = smem_u32(smem);
    const uint32_t uAh = sb;
    const uint32_t uAl = sb + TILEB;

    const int t = threadIdx.x;
    const int wid = t >> 5, lane = t & 31;
    const int wm = wid >> 1, wn = wid & 1;      // warp grid 4x2 (per-B N=128)
    const int m0 = blockIdx.x * 128;

    const __nv_bfloat16* Barr[4] = {B0hi, B0lo, B1hi, B1lo};

    float acc[2][2][8][4];                      // [mat][mt][nt][q]
    #pragma unroll
    for (int m = 0; m < 2; ++m)
        #pragma unroll
        for (int mt = 0; mt < 2; ++mt)
            #pragma unroll
            for (int nt = 0; nt < 8; ++nt)
                #pragma unroll
                for (int q = 0; q < 4; ++q) acc[m][mt][nt][q] = 0.f;

    const int srow = t >> 1;         // staging row 0..127
    const int shalf = t & 1;         // k-half within 32-chunk
    const bool valid = (m0 + srow) < M;

    float fr[16];                    // prefetched A chunk (fp32)

    // ---- helpers as lambdas ----
    auto loadA = [&](int c) {
        const float* Asrc = (c < 4) ? A1 : A2;
        const float4* ap = (const float4*)(Asrc + (size_t)(m0 + srow) * 128
                                           + (c & 3) * 32 + shalf * 16);
        #pragma unroll
        for (int j = 0; j < 4; ++j) {
            float4 v = valid ? ap[j] : make_float4(0.f, 0.f, 0.f, 0.f);
            fr[4 * j] = v.x; fr[4 * j + 1] = v.y; fr[4 * j + 2] = v.z; fr[4 * j + 3] = v.w;
        }
    };
    auto writeA = [&]() {
        uint32_t hw[8], lw[8];
        #pragma unroll
        for (int q = 0; q < 8; ++q) {
            float a = fr[2 * q], b = fr[2 * q + 1];
            float ah = __bfloat162float(__float2bfloat16_rn(a));
            float bh = __bfloat162float(__float2bfloat16_rn(b));
            hw[q] = packbf2(a, b);
            lw[q] = packbf2(a - ah, b - bh);
        }
        int off = srow * ROWB + shalf * 32;
        *(uint4*)(smem + off)              = make_uint4(hw[0], hw[1], hw[2], hw[3]);
        *(uint4*)(smem + off + 16)         = make_uint4(hw[4], hw[5], hw[6], hw[7]);
        *(uint4*)(smem + TILEB + off)      = make_uint4(lw[0], lw[1], lw[2], lw[3]);
        *(uint4*)(smem + TILEB + off + 16) = make_uint4(lw[4], lw[5], lw[6], lw[7]);
    };
    auto stageB = [&](int c, int buf) {
        #pragma unroll
        for (int j = 0; j < 8; ++j) {
            int i = t + j * 256;             // 0..2047
            int arr = i >> 9;                // 4 arrays, 512 transfers each
            int r = (i >> 2) & 127;
            int q = i & 3;
            uint32_t dst = sb + SB_OFF + (uint32_t)(arr * 2 + buf) * TILEB
                           + r * ROWB + q * 16;
            const char* src = (const char*)(Barr[arr] + (size_t)r * 256 + c * 32) + q * 16;
            cpa16(dst, src);
        }
    };

    // ---- prologue: stage chunk 0 ----
    loadA(0);
    stageB(0, 0);
    cp_commit();
    writeA();
    cp_wait0();
    __syncthreads();

    const int arow = wm * 32 + (lane & 15);
    const int brow = wn * 64 + (lane & 7);

    for (int c = 0; c < 8; ++c) {
        if (c < 7) {
            stageB(c + 1, (c + 1) & 1);
            cp_commit();
            loadA(c + 1);
        }
        const uint32_t bufo = SB_OFF + (uint32_t)(c & 1) * TILEB;
        // ---- compute on chunk c ----
        #pragma unroll
        for (int ks = 0; ks < 2; ++ks) {
            uint32_t ah[2][4], al[2][4];
            const int akb = ks * 32 + (lane >> 4) * 16;
            #pragma unroll
            for (int mt = 0; mt < 2; ++mt) {
                uint32_t ao = (uint32_t)((arow + mt * 16) * ROWB + akb);
                ldmx4(ah[mt], uAh + ao);
                ldmx4(al[mt], uAl + ao);
            }
            const int bkb = ks * 32 + ((lane >> 3) & 1) * 16;
            #pragma unroll
            for (int nt = 0; nt < 8; ++nt) {
                uint32_t ro = (uint32_t)((brow + nt * 8) * ROWB + bkb);
                #pragma unroll
                for (int m = 0; m < 2; ++m) {
                    uint32_t bh[2], bl[2];
                    ldmx2(bh, sb + bufo + (uint32_t)(m * 4) * TILEB + ro);
                    ldmx2(bl, sb + bufo + (uint32_t)(m * 4 + 2) * TILEB + ro);
                    #pragma unroll
                    for (int mt = 0; mt < 2; ++mt) {
                        mma16816(acc[m][mt][nt], ah[mt], bh);
                        mma16816(acc[m][mt][nt], ah[mt], bl);
                        mma16816(acc[m][mt][nt], al[mt], bh);
                    }
                }
            }
        }
        __syncthreads();            // all reads of sA/sB(c) done
        if (c < 7) {
            writeA();               // stage A(c+1) from prefetched regs
            cp_wait0();             // B(c+1) arrived
        }
        __syncthreads();
    }

    // ---- epilogue ----
    const int g = lane >> 2, tig = lane & 3;
    #pragma unroll
    for (int m = 0; m < 2; ++m) {
        float* C = m ? C1 : C0;
        const float* bias = m ? bias1 : bias0;
        #pragma unroll
        for (int mt = 0; mt < 2; ++mt) {
            #pragma unroll
            for (int nt = 0; nt < 8; ++nt) {
                int col = wn * 64 + nt * 8 + tig * 2;
                float bx = 0.f, by = 0.f;
                if (GATES) { bx = __ldg(bias + col); by = __ldg(bias + col + 1); }
                #pragma unroll
                for (int s = 0; s < 2; ++s) {
                    int r = m0 + wm * 32 + mt * 16 + g + s * 8;
                    if (r < M) {
                        float v0 = acc[m][mt][nt][2 * s], v1 = acc[m][mt][nt][2 * s + 1];
                        if (GATES) {
                            v0 = sgm(v0 + bx); v1 = sgm(v1 + by);
                            if (m == 1) {
                                const float2 hv = *(const float2*)(H + (size_t)r * 128 + col);
                                v0 *= hv.x; v1 *= hv.y;
                            }
                        }
                        *(float2*)(C + (size_t)r * 128 + col) = make_float2(v0, v1);
                    }
                }
            }
        }
    }
}

// One warp per edge: vectorized RED (v4.f32) of y[src] into agg[dst].
__global__ void __launch_bounds__(256) scatter_kernel(
    const int* __restrict__ ei, const float* __restrict__ y,
    float* __restrict__ agg, int* __restrict__ cnt, int E)
{
    int gw = (int)((blockIdx.x * 256u + threadIdx.x) >> 5);
    int lane = threadIdx.x & 31;
    if (gw >= E) return;
    int src = __ldg(ei + gw);
    int dst = __ldg(ei + E + gw);
    float4 v = *(const float4*)(y + (size_t)src * 128 + lane * 4);
    float* a = agg + (size_t)dst * 128 + lane * 4;
    asm volatile("red.global.add.v4.f32 [%0], {%1, %2, %3, %4};"
                 :: "l"(a), "f"(v.x), "f"(v.y), "f"(v.z), "f"(v.w) : "memory");
    if (lane == 0) atomicAdd(cnt + dst, 1);
}

// out = (1-z) * (agg/max(cnt,1) + b_l + w) + z * h
__global__ void __launch_bounds__(256) final_kernel(
    const float* __restrict__ z, const float* __restrict__ w,
    const float* __restrict__ agg, const int* __restrict__ cnt,
    const float* __restrict__ b_l, const float* __restrict__ h,
    float* __restrict__ out, int M)
{
    int i4 = blockIdx.x * 256 + threadIdx.x;
    if (i4 >= M * 32) return;
    int node = i4 >> 5;
    int c4 = i4 & 31;
    float inv = 1.f / fmaxf((float)__ldg(cnt + node), 1.f);
    size_t off = (size_t)i4 * 4;
    float4 zv = *(const float4*)(z + off);
    float4 wv = *(const float4*)(w + off);
    float4 av = *(const float4*)(agg + off);
    float4 hv = *(const float4*)(h + off);
    float4 bv = *(const float4*)(b_l + c4 * 4);
    float4 o;
    o.x = (1.f - zv.x) * (av.x * inv + bv.x + wv.x) + zv.x * hv.x;
    o.y = (1.f - zv.y) * (av.y * inv + bv.y + wv.y) + zv.y * hv.y;
    o.z = (1.f - zv.z) * (av.z * inv + bv.z + wv.z) + zv.z * hv.z;
    o.w = (1.f - zv.w) * (av.w * inv + bv.w + wv.w) + zv.w * hv.w;
    *(float4*)(out + off) = o;
}

extern "C" void kernel_launch(void* const* d_in, const int* in_sizes, int n_in,
                              void* d_out, int out_size)
{
    const float* x    = (const float*)d_in[0];
    const int*   ei   = (const int*)d_in[1];
    const float* h    = (const float*)d_in[2];
    const float* W_xr = (const float*)d_in[3];
    const float* b_xr = (const float*)d_in[4];
    const float* W_hr = (const float*)d_in[5];
    const float* W_xz = (const float*)d_in[6];
    const float* b_xz = (const float*)d_in[7];
    const float* W_hz = (const float*)d_in[8];
    const float* W_l  = (const float*)d_in[9];
    const float* b_l  = (const float*)d_in[10];
    const float* W_r  = (const float*)d_in[11];
    float* out = (float*)d_out;

    const int M = in_sizes[0] / 128;
    const int E = in_sizes[1] / 2;
    const size_t ND = (size_t)M * 128;

    void* ps = nullptr; cudaGetSymbolAddress(&ps, g_scratch);
    void* pc = nullptr; cudaGetSymbolAddress(&pc, g_cnt);
    void* pw = nullptr; cudaGetSymbolAddress(&pw, g_wbuf);
    float* z   = (float*)ps;
    float* rh  = z  + ND;
    float* y   = rh + ND;
    float* w   = y  + ND;
    float* agg = w  + ND;
    int*   cnt = (int*)pc;
    __nv_bfloat16* wbuf = (__nv_bfloat16*)pw;

    static int attr_done = 0;
    if (!attr_done) {
        cudaFuncSetAttribute(gemm_dual2<0>, cudaFuncAttributeMaxDynamicSharedMemorySize, SMEMSZ);
        cudaFuncSetAttribute(gemm_dual2<1>, cudaFuncAttributeMaxDynamicSharedMemorySize, SMEMSZ);
        attr_done = 1;
    }

    cudaMemsetAsync(agg, 0, ND * sizeof(float), 0);
    cudaMemsetAsync(cnt, 0, M * sizeof(int), 0);

    // Prep weights: mat0=(W_xz|W_hz), mat1=(W_xr|W_hr), mat2=W_l, mat3=W_r
    prep_w<<<512, 256>>>(W_xz, W_hz, W_xr, W_hr, W_l, W_r, wbuf);

    __nv_bfloat16* BZ_hi = wbuf;
    __nv_bfloat16* BZ_lo = wbuf + 1 * 32768;
    __nv_bfloat16* BR_hi = wbuf + 2 * 32768;
    __nv_bfloat16* BR_lo = wbuf + 3 * 32768;
    __nv_bfloat16* BL_hi = wbuf + 4 * 32768;
    __nv_bfloat16* BL_lo = wbuf + 5 * 32768;
    __nv_bfloat16* BW_hi = wbuf + 6 * 32768;
    __nv_bfloat16* BW_lo = wbuf + 7 * 32768;

    int gb = (M + 127) / 128;
    // z = sigmoid([x|h]@Wz + b_xz) ; rh = sigmoid([x|h]@Wr + b_xr) * h
    gemm_dual2<1><<<gb, 256, SMEMSZ>>>(x, h, BZ_hi, BZ_lo, BR_hi, BR_lo,
                                       b_xz, b_xr, h, z, rh, M);
    // y = [x|rh]@W_l ; w = [x|rh]@W_r
    gemm_dual2<0><<<gb, 256, SMEMSZ>>>(x, rh, BL_hi, BL_lo, BW_hi, BW_lo,
                                       nullptr, nullptr, nullptr, y, w, M);

    scatter_kernel<<<(E + 7) / 8, 256>>>(ei, y, agg, cnt, E);

    final_kernel<<<(M * 32 + 255) / 256, 256>>>(z, w, agg, cnt, b_l, h, out, M);
}

// round 6
// speedup vs baseline: 3.0232x; 1.0046x over previous
#include <cuda_runtime.h>
#include <cuda_bf16.h>
#include <math.h>
#include <stdint.h>

#define NMAX 50048
typedef unsigned long long u64;

// Scratch: z, y, w, agg (4 x N x 128 fp32) + counts
__device__ float g_scratch[(size_t)NMAX * 128 * 4];
__device__ int g_cnt[NMAX];
// 4 weight matrices x {hi,lo} x [128 n][256 k] bf16
__device__ __nv_bfloat16 g_wbuf[8 * 128 * 256];
// A operand buffers: {a1hi, a1lo, a2hi, a2lo} x [NMAX rows][256 k] bf16
__device__ __nv_bfloat16 g_abuf[4][(size_t)NMAX * 256];

__device__ __forceinline__ float sgm(float x) { return 1.f / (1.f + __expf(-x)); }

__device__ __forceinline__ uint32_t smem_u32(const void* p) {
    uint32_t a;
    asm("{ .reg .u64 t; cvta.to.shared.u64 t, %1; cvt.u32.u64 %0, t; }" : "=r"(a) : "l"(p));
    return a;
}
__device__ __forceinline__ void ldmx4(uint32_t* r, uint32_t addr) {
    asm volatile("ldmatrix.sync.aligned.m8n8.x4.shared.b16 {%0,%1,%2,%3}, [%4];"
                 : "=r"(r[0]), "=r"(r[1]), "=r"(r[2]), "=r"(r[3]) : "r"(addr));
}
__device__ __forceinline__ void ldmx2(uint32_t* r, uint32_t addr) {
    asm volatile("ldmatrix.sync.aligned.m8n8.x2.shared.b16 {%0,%1}, [%2];"
                 : "=r"(r[0]), "=r"(r[1]) : "r"(addr));
}
__device__ __forceinline__ void mma16816(float* c, const uint32_t* a, const uint32_t* b) {
    asm volatile(
        "mma.sync.aligned.m16n8k16.row.col.f32.bf16.bf16.f32 "
        "{%0,%1,%2,%3}, {%4,%5,%6,%7}, {%8,%9}, {%0,%1,%2,%3};"
        : "+f"(c[0]), "+f"(c[1]), "+f"(c[2]), "+f"(c[3])
        : "r"(a[0]), "r"(a[1]), "r"(a[2]), "r"(a[3]), "r"(b[0]), "r"(b[1]));
}
__device__ __forceinline__ uint32_t packbf2(float a, float b) {
    __nv_bfloat162 p = __halves2bfloat162(__float2bfloat16_rn(a), __float2bfloat16_rn(b));
    return *(uint32_t*)&p;
}
__device__ __forceinline__ void cpa16(uint32_t dst, const void* src) {
    asm volatile("cp.async.ca.shared.global [%0], [%1], 16;" :: "r"(dst), "l"(src) : "memory");
}
__device__ __forceinline__ void cp_commit() { asm volatile("cp.async.commit_group;" ::: "memory"); }

// ---------------------------------------------------------------------------
// Weight prep: 4 logical [256,128] fp32 matrices -> transposed [128 n][256 k]
// bf16 hi/lo split. mat 0: (W_xz|W_hz)  1: (W_xr|W_hr)  2: W_l  3: W_r(sage)
// ---------------------------------------------------------------------------
__global__ void __launch_bounds__(256) prep_w(
    const float* __restrict__ W0x, const float* __restrict__ W0h,
    const float* __restrict__ W1x, const float* __restrict__ W1h,
    const float* __restrict__ W2, const float* __restrict__ W3,
    __nv_bfloat16* __restrict__ wbuf)
{
    int i = blockIdx.x * 256 + threadIdx.x;   // 4 * 32768
    int mat = i >> 15;
    int r = i & 32767;
    int n = r >> 8, k = r & 255;
    const float *Wx, *Wh;
    if (mat == 0)      { Wx = W0x; Wh = W0h; }
    else if (mat == 1) { Wx = W1x; Wh = W1h; }
    else if (mat == 2) { Wx = W2;  Wh = W2 + 16384; }
    else               { Wx = W3;  Wh = W3 + 16384; }
    float w = (k < 128) ? Wx[(size_t)k * 128 + n] : Wh[(size_t)(k - 128) * 128 + n];
    __nv_bfloat16 hi = __float2bfloat16_rn(w);
    __nv_bfloat16 lo = __float2bfloat16_rn(w - __bfloat162float(hi));
    wbuf[(size_t)(2 * mat) * 32768 + n * 256 + k] = hi;
    wbuf[(size_t)(2 * mat + 1) * 32768 + n * 256 + k] = lo;
}

// ---------------------------------------------------------------------------
// A prep: x -> abuf1[:,0:128] and abuf2[:,0:128]; h -> abuf1[:,128:256].
// bf16 hi/lo split, 4 k per thread.
// ---------------------------------------------------------------------------
__global__ void __launch_bounds__(256) prep_a(
    const float* __restrict__ x, const float* __restrict__ h,
    __nv_bfloat16* __restrict__ a1hi, __nv_bfloat16* __restrict__ a1lo,
    __nv_bfloat16* __restrict__ a2hi, __nv_bfloat16* __restrict__ a2lo, int M)
{
    int i = blockIdx.x * 256 + threadIdx.x;
    if (i >= M * 32) return;
    int r = i >> 5, kq = i & 31;
    size_t so = (size_t)r * 128 + kq * 4;
    size_t dox = (size_t)r * 256 + kq * 4;
    size_t doh = dox + 128;
    float4 xv = *(const float4*)(x + so);
    float4 hv = *(const float4*)(h + so);
    float fx[4] = {xv.x, xv.y, xv.z, xv.w};
    float fh[4] = {hv.x, hv.y, hv.z, hv.w};
    uint32_t xh[2], xl[2], hh[2], hl[2];
    #pragma unroll
    for (int q = 0; q < 2; ++q) {
        float a = fx[2 * q], b = fx[2 * q + 1];
        float ah = __bfloat162float(__float2bfloat16_rn(a));
        float bh = __bfloat162float(__float2bfloat16_rn(b));
        xh[q] = packbf2(a, b); xl[q] = packbf2(a - ah, b - bh);
        a = fh[2 * q]; b = fh[2 * q + 1];
        ah = __bfloat162float(__float2bfloat16_rn(a));
        bh = __bfloat162float(__float2bfloat16_rn(b));
        hh[q] = packbf2(a, b); hl[q] = packbf2(a - ah, b - bh);
    }
    *(uint2*)(a1hi + dox) = make_uint2(xh[0], xh[1]);
    *(uint2*)(a1lo + dox) = make_uint2(xl[0], xl[1]);
    *(uint2*)(a2hi + dox) = make_uint2(xh[0], xh[1]);
    *(uint2*)(a2lo + dox) = make_uint2(xl[0], xl[1]);
    *(uint2*)(a1hi + doh) = make_uint2(hh[0], hh[1]);
    *(uint2*)(a1lo + doh) = make_uint2(hl[0], hl[1]);
}

// ---------------------------------------------------------------------------
// Fused dual-B HMMA GEMM, pure-bf16 cp.async pipeline (2-stage double buffer).
//   acc0 = A @ W0,  acc1 = A @ W1   (A = prepped hi/lo, [row][256k])
// 3-term split: AhBh + AhBl + AlBh, fp32 accum.
// GATES=1: C0 = sigmoid(acc0+bias0) (z);  rh = sigmoid(acc1+bias1)*H written
//          as bf16 hi/lo into Rhi/Rlo cols 128:256 (gemm2's A buffer).
// GATES=0: C0 = acc0 (y), C1 = acc1 (w).
// 512 threads, warp grid 8(m)x2(n), warp tile 16x64 per matrix.
// ---------------------------------------------------------------------------
#define ROWB 80
#define ATILE (128 * ROWB)            // 10240 B per array per buffer
#define NARR 6                        // Ahi,Alo,B0hi,B0lo,B1hi,B1lo
#define SMEMSZ (2 * NARR * ATILE)     // 122880 B

template <int GATES>
__global__ void __launch_bounds__(512, 1) gemm_dual2(
    const __nv_bfloat16* __restrict__ Ahi, const __nv_bfloat16* __restrict__ Alo,
    const __nv_bfloat16* __restrict__ B0hi, const __nv_bfloat16* __restrict__ B0lo,
    const __nv_bfloat16* __restrict__ B1hi, const __nv_bfloat16* __restrict__ B1lo,
    const float* __restrict__ bias0, const float* __restrict__ bias1,
    const float* __restrict__ H,
    float* __restrict__ C0, float* __restrict__ C1,
    __nv_bfloat16* __restrict__ Rhi, __nv_bfloat16* __restrict__ Rlo, int M)
{
    extern __shared__ __align__(16) char smem[];
    const uint32_t sb = smem_u32(smem);

    const int t = threadIdx.x;
    const int wid = t >> 5, lane = t & 31;
    const int wm = wid >> 1, wn = wid & 1;      // warp grid 8x2
    const int m0 = blockIdx.x * 128;

    const __nv_bfloat16* arrs[6] = {Ahi, Alo, B0hi, B0lo, B1hi, B1lo};

    float acc[2][8][4];                         // [mat][nt][q]
    #pragma unroll
    for (int m = 0; m < 2; ++m)
        #pragma unroll
        for (int nt = 0; nt < 8; ++nt)
            #pragma unroll
            for (int q = 0; q < 4; ++q) acc[m][nt][q] = 0.f;

    const int sr = t >> 2, sq = t & 3;          // staging: row, 16B quarter

    auto stage = [&](int c, int b) {
        uint32_t base = sb + (uint32_t)b * (NARR * ATILE) + sr * ROWB + sq * 16;
        size_t go = (size_t)sr * 256 + c * 32 + sq * 8;   // A rows; B n-rows
        size_t ga = (size_t)(m0 + sr) * 256 + c * 32 + sq * 8;
        cpa16(base + 0 * ATILE, arrs[0] + ga);
        cpa16(base + 1 * ATILE, arrs[1] + ga);
        #pragma unroll
        for (int j = 0; j < 4; ++j)
            cpa16(base + (2 + j) * ATILE, arrs[2 + j] + go);
    };

    stage(0, 0); cp_commit();
    stage(1, 1); cp_commit();

    const int arow = wm * 16 + (lane & 15);
    const int brow = wn * 64 + (lane & 7);

    for (int c = 0; c < 8; ++c) {
        if (c < 7) asm volatile("cp.async.wait_group 1;" ::: "memory");
        else       asm volatile("cp.async.wait_group 0;" ::: "memory");
        __syncthreads();
        const uint32_t bufo = sb + (uint32_t)(c & 1) * (NARR * ATILE);
        #pragma unroll
        for (int ks = 0; ks < 2; ++ks) {
            uint32_t ah[4], al[4];
            const int akb = ks * 32 + (lane >> 4) * 16;
            uint32_t ao = (uint32_t)(arow * ROWB + akb);
            ldmx4(ah, bufo + ao);
            ldmx4(al, bufo + ATILE + ao);
            const int bkb = ks * 32 + ((lane >> 3) & 1) * 16;
            #pragma unroll
            for (int nt = 0; nt < 8; ++nt) {
                uint32_t ro = (uint32_t)((brow + nt * 8) * ROWB + bkb);
                #pragma unroll
                for (int m = 0; m < 2; ++m) {
                    uint32_t bh[2], bl[2];
                    ldmx2(bh, bufo + (uint32_t)(2 + 2 * m) * ATILE + ro);
                    ldmx2(bl, bufo + (uint32_t)(3 + 2 * m) * ATILE + ro);
                    mma16816(acc[m][nt], ah, bh);
                    mma16816(acc[m][nt], ah, bl);
                    mma16816(acc[m][nt], al, bh);
                }
            }
        }
        if (c < 6) {
            __syncthreads();          // everyone done reading buf (c&1)
            stage(c + 2, c & 1);
            cp_commit();
        }
    }

    // ---- epilogue ----
    const int g = lane >> 2, tig = lane & 3;
    #pragma unroll
    for (int m = 0; m < 2; ++m) {
        const float* bias = m ? bias1 : bias0;
        #pragma unroll
        for (int nt = 0; nt < 8; ++nt) {
            int col = wn * 64 + nt * 8 + tig * 2;
            float bx = 0.f, by = 0.f;
            if (GATES) { bx = __ldg(bias + col); by = __ldg(bias + col + 1); }
            #pragma unroll
            for (int s = 0; s < 2; ++s) {
                int r = m0 + wm * 16 + g + s * 8;
                if (r < M) {
                    float v0 = acc[m][nt][2 * s], v1 = acc[m][nt][2 * s + 1];
                    if (GATES == 0) {
                        float* C = m ? C1 : C0;
                        *(float2*)(C + (size_t)r * 128 + col) = make_float2(v0, v1);
                    } else if (m == 0) {
                        v0 = sgm(v0 + bx); v1 = sgm(v1 + by);
                        *(float2*)(C0 + (size_t)r * 128 + col) = make_float2(v0, v1);
                    } else {
                        const float2 hv = *(const float2*)(H + (size_t)r * 128 + col);
                        float r0 = sgm(v0 + bx) * hv.x;
                        float r1 = sgm(v1 + by) * hv.y;
                        float h0 = __bfloat162float(__float2bfloat16_rn(r0));
                        float h1 = __bfloat162float(__float2bfloat16_rn(r1));
                        size_t doo = (size_t)r * 256 + 128 + col;
                        *(uint32_t*)(Rhi + doo) = packbf2(r0, r1);
                        *(uint32_t*)(Rlo + doo) = packbf2(r0 - h0, r1 - h1);
                    }
                }
            }
        }
    }
}

// One warp per edge: vectorized RED (v4.f32) of y[src] into agg[dst].
__global__ void __launch_bounds__(256) scatter_kernel(
    const int* __restrict__ ei, const float* __restrict__ y,
    float* __restrict__ agg, int* __restrict__ cnt, int E)
{
    int gw = (int)((blockIdx.x * 256u + threadIdx.x) >> 5);
    int lane = threadIdx.x & 31;
    if (gw >= E) return;
    int src = __ldg(ei + gw);
    int dst = __ldg(ei + E + gw);
    float4 v = *(const float4*)(y + (size_t)src * 128 + lane * 4);
    float* a = agg + (size_t)dst * 128 + lane * 4;
    asm volatile("red.global.add.v4.f32 [%0], {%1, %2, %3, %4};"
                 :: "l"(a), "f"(v.x), "f"(v.y), "f"(v.z), "f"(v.w) : "memory");
    if (lane == 0) atomicAdd(cnt + dst, 1);
}

// out = (1-z) * (agg/max(cnt,1) + b_l + w) + z * h
__global__ void __launch_bounds__(256) final_kernel(
    const float* __restrict__ z, const float* __restrict__ w,
    const float* __restrict__ agg, const int* __restrict__ cnt,
    const float* __restrict__ b_l, const float* __restrict__ h,
    float* __restrict__ out, int M)
{
    int i4 = blockIdx.x * 256 + threadIdx.x;
    if (i4 >= M * 32) return;
    int node = i4 >> 5;
    int c4 = i4 & 31;
    float inv = 1.f / fmaxf((float)__ldg(cnt + node), 1.f);
    size_t off = (size_t)i4 * 4;
    float4 zv = *(const float4*)(z + off);
    float4 wv = *(const float4*)(w + off);
    float4 av = *(const float4*)(agg + off);
    float4 hv = *(const float4*)(h + off);
    float4 bv = *(const float4*)(b_l + c4 * 4);
    float4 o;
    o.x = (1.f - zv.x) * (av.x * inv + bv.x + wv.x) + zv.x * hv.x;
    o.y = (1.f - zv.y) * (av.y * inv + bv.y + wv.y) + zv.y * hv.y;
    o.z = (1.f - zv.z) * (av.z * inv + bv.z + wv.z) + zv.z * hv.z;
    o.w = (1.f - zv.w) * (av.w * inv + bv.w + wv.w) + zv.w * hv.w;
    *(float4*)(out + off) = o;
}

extern "C" void kernel_launch(void* const* d_in, const int* in_sizes, int n_in,
                              void* d_out, int out_size)
{
    const float* x    = (const float*)d_in[0];
    const int*   ei   = (const int*)d_in[1];
    const float* h    = (const float*)d_in[2];
    const float* W_xr = (const float*)d_in[3];
    const float* b_xr = (const float*)d_in[4];
    const float* W_hr = (const float*)d_in[5];
    const float* W_xz = (const float*)d_in[6];
    const float* b_xz = (const float*)d_in[7];
    const float* W_hz = (const float*)d_in[8];
    const float* W_l  = (const float*)d_in[9];
    const float* b_l  = (const float*)d_in[10];
    const float* W_r  = (const float*)d_in[11];
    float* out = (float*)d_out;

    const int M = in_sizes[0] / 128;
    const int E = in_sizes[1] / 2;
    const size_t ND = (size_t)M * 128;

    void* ps = nullptr; cudaGetSymbolAddress(&ps, g_scratch);
    void* pc = nullptr; cudaGetSymbolAddress(&pc, g_cnt);
    void* pw = nullptr; cudaGetSymbolAddress(&pw, g_wbuf);
    void* pa = nullptr; cudaGetSymbolAddress(&pa, g_abuf);
    float* z   = (float*)ps;
    float* y   = z + ND;
    float* w   = y + ND;
    float* agg = w + ND;
    int*   cnt = (int*)pc;
    __nv_bfloat16* wbuf = (__nv_bfloat16*)pw;
    __nv_bfloat16* a1hi = (__nv_bfloat16*)pa;
    __nv_bfloat16* a1lo = a1hi + (size_t)NMAX * 256;
    __nv_bfloat16* a2hi = a1lo + (size_t)NMAX * 256;
    __nv_bfloat16* a2lo = a2hi + (size_t)NMAX * 256;

    cudaFuncSetAttribute(gemm_dual2<0>, cudaFuncAttributeMaxDynamicSharedMemorySize, SMEMSZ);
    cudaFuncSetAttribute(gemm_dual2<1>, cudaFuncAttributeMaxDynamicSharedMemorySize, SMEMSZ);

    cudaMemsetAsync(agg, 0, ND * sizeof(float), 0);
    cudaMemsetAsync(cnt, 0, M * sizeof(int), 0);

    // Prep: weights + A operands (x, h -> bf16 hi/lo)
    prep_w<<<512, 256>>>(W_xz, W_hz, W_xr, W_hr, W_l, W_r, wbuf);
    prep_a<<<(M * 32 + 255) / 256, 256>>>(x, h, a1hi, a1lo, a2hi, a2lo, M);

    __nv_bfloat16* BZ_hi = wbuf;
    __nv_bfloat16* BZ_lo = wbuf + 1 * 32768;
    __nv_bfloat16* BR_hi = wbuf + 2 * 32768;
    __nv_bfloat16* BR_lo = wbuf + 3 * 32768;
    __nv_bfloat16* BL_hi = wbuf + 4 * 32768;
    __nv_bfloat16* BL_lo = wbuf + 5 * 32768;
    __nv_bfloat16* BW_hi = wbuf + 6 * 32768;
    __nv_bfloat16* BW_lo = wbuf + 7 * 32768;

    int gb = (M + 127) / 128;
    // z = sigmoid([x|h]@Wz + b_xz) ; rh(bf16 split) = sigmoid([x|h]@Wr + b_xr)*h
    gemm_dual2<1><<<gb, 512, SMEMSZ>>>(a1hi, a1lo, BZ_hi, BZ_lo, BR_hi, BR_lo,
                                       b_xz, b_xr, h, z, nullptr, a2hi, a2lo, M);
    // y = [x|rh]@W_l ; w = [x|rh]@W_r
    gemm_dual2<0><<<gb, 512, SMEMSZ>>>(a2hi, a2lo, BL_hi, BL_lo, BW_hi, BW_lo,
                                       nullptr, nullptr, nullptr, y, w, nullptr, nullptr, M);

    scatter_kernel<<<(E + 7) / 8, 256>>>(ei, y, agg, cnt, E);

    final_kernel<<<(M * 32 + 255) / 256, 256>>>(z, w, agg, cnt, b_l, h, out, M);
}

// round 8
// speedup vs baseline: 3.6184x; 1.1969x over previous
#include <cuda_runtime.h>
#include <cuda_bf16.h>
#include <math.h>
#include <stdint.h>

#define NMAX 50048
#define EMAX 803072
typedef unsigned long long u64;

// Scratch: z, y, w, agg (4 x N x 128 fp32)
__device__ float g_scratch[(size_t)NMAX * 128 * 4];
__device__ int g_cnt[NMAX];     // in-degree (== mean denominator)
__device__ int g_off[NMAX];     // CSR exclusive offsets
__device__ int g_pos[NMAX];     // fill cursors
__device__ int g_ebuf[EMAX];    // CSR: src node per slot
__device__ int g_bsum[256];     // scan block sums
// 4 weight matrices x {hi,lo} x [128 n][256 k] bf16
__device__ __nv_bfloat16 g_wbuf[8 * 128 * 256];
// A operand buffers: {a1hi, a1lo, a2hi, a2lo} x [NMAX rows][256 k] bf16
__device__ __nv_bfloat16 g_abuf[4][(size_t)NMAX * 256];

__device__ __forceinline__ float sgm(float x) { return 1.f / (1.f + __expf(-x)); }

__device__ __forceinline__ uint32_t smem_u32(const void* p) {
    uint32_t a;
    asm("{ .reg .u64 t; cvta.to.shared.u64 t, %1; cvt.u32.u64 %0, t; }" : "=r"(a) : "l"(p));
    return a;
}
__device__ __forceinline__ void ldmx4(uint32_t* r, uint32_t addr) {
    asm volatile("ldmatrix.sync.aligned.m8n8.x4.shared.b16 {%0,%1,%2,%3}, [%4];"
                 : "=r"(r[0]), "=r"(r[1]), "=r"(r[2]), "=r"(r[3]) : "r"(addr));
}
__device__ __forceinline__ void mma16816(float* c, const uint32_t* a, const uint32_t* b) {
    asm volatile(
        "mma.sync.aligned.m16n8k16.row.col.f32.bf16.bf16.f32 "
        "{%0,%1,%2,%3}, {%4,%5,%6,%7}, {%8,%9}, {%0,%1,%2,%3};"
        : "+f"(c[0]), "+f"(c[1]), "+f"(c[2]), "+f"(c[3])
        : "r"(a[0]), "r"(a[1]), "r"(a[2]), "r"(a[3]), "r"(b[0]), "r"(b[1]));
}
__device__ __forceinline__ uint32_t packbf2(float a, float b) {
    __nv_bfloat162 p = __halves2bfloat162(__float2bfloat16_rn(a), __float2bfloat16_rn(b));
    return *(uint32_t*)&p;
}
__device__ __forceinline__ void cpa16(uint32_t dst, const void* src) {
    asm volatile("cp.async.ca.shared.global [%0], [%1], 16;" :: "r"(dst), "l"(src) : "memory");
}
__device__ __forceinline__ void cp_commit() { asm volatile("cp.async.commit_group;" ::: "memory"); }

// ---------------------------------------------------------------------------
// Weight prep (unchanged): 4 x [256,128] fp32 -> transposed [128 n][256 k] hi/lo
// ---------------------------------------------------------------------------
__global__ void __launch_bounds__(256) prep_w(
    const float* __restrict__ W0x, const float* __restrict__ W0h,
    const float* __restrict__ W1x, const float* __restrict__ W1h,
    const float* __restrict__ W2, const float* __restrict__ W3,
    __nv_bfloat16* __restrict__ wbuf)
{
    int i = blockIdx.x * 256 + threadIdx.x;
    int mat = i >> 15;
    int r = i & 32767;
    int n = r >> 8, k = r & 255;
    const float *Wx, *Wh;
    if (mat == 0)      { Wx = W0x; Wh = W0h; }
    else if (mat == 1) { Wx = W1x; Wh = W1h; }
    else if (mat == 2) { Wx = W2;  Wh = W2 + 16384; }
    else               { Wx = W3;  Wh = W3 + 16384; }
    float w = (k < 128) ? Wx[(size_t)k * 128 + n] : Wh[(size_t)(k - 128) * 128 + n];
    __nv_bfloat16 hi = __float2bfloat16_rn(w);
    __nv_bfloat16 lo = __float2bfloat16_rn(w - __bfloat162float(hi));
    wbuf[(size_t)(2 * mat) * 32768 + n * 256 + k] = hi;
    wbuf[(size_t)(2 * mat + 1) * 32768 + n * 256 + k] = lo;
}

// A prep: x -> abuf1/abuf2 cols 0:128; h -> abuf1 cols 128:256 (hi/lo split)
__global__ void __launch_bounds__(256) prep_a(
    const float* __restrict__ x, const float* __restrict__ h,
    __nv_bfloat16* __restrict__ a1hi, __nv_bfloat16* __restrict__ a1lo,
    __nv_bfloat16* __restrict__ a2hi, __nv_bfloat16* __restrict__ a2lo, int M)
{
    int i = blockIdx.x * 256 + threadIdx.x;
    if (i >= M * 32) return;
    int r = i >> 5, kq = i & 31;
    size_t so = (size_t)r * 128 + kq * 4;
    size_t dox = (size_t)r * 256 + kq * 4;
    size_t doh = dox + 128;
    float4 xv = *(const float4*)(x + so);
    float4 hv = *(const float4*)(h + so);
    float fx[4] = {xv.x, xv.y, xv.z, xv.w};
    float fh[4] = {hv.x, hv.y, hv.z, hv.w};
    uint32_t xh[2], xl[2], hh[2], hl[2];
    #pragma unroll
    for (int q = 0; q < 2; ++q) {
        float a = fx[2 * q], b = fx[2 * q + 1];
        float ah = __bfloat162float(__float2bfloat16_rn(a));
        float bh = __bfloat162float(__float2bfloat16_rn(b));
        xh[q] = packbf2(a, b); xl[q] = packbf2(a - ah, b - bh);
        a = fh[2 * q]; b = fh[2 * q + 1];
        ah = __bfloat162float(__float2bfloat16_rn(a));
        bh = __bfloat162float(__float2bfloat16_rn(b));
        hh[q] = packbf2(a, b); hl[q] = packbf2(a - ah, b - bh);
    }
    *(uint2*)(a1hi + dox) = make_uint2(xh[0], xh[1]);
    *(uint2*)(a1lo + dox) = make_uint2(xl[0], xl[1]);
    *(uint2*)(a2hi + dox) = make_uint2(xh[0], xh[1]);
    *(uint2*)(a2lo + dox) = make_uint2(xl[0], xl[1]);
    *(uint2*)(a1hi + doh) = make_uint2(hh[0], hh[1]);
    *(uint2*)(a1lo + doh) = make_uint2(hl[0], hl[1]);
}

// ---------------------------------------------------------------------------
// Fused dual-B HMMA GEMM. Warp grid 4x4 (warp tile 32m x 32n per matrix).
// B fragments loaded pairwise with ldmatrix.x4 => 12 LDSM per 48 MMA.
// 3-term split (AhBh + AhBl + AlBh), fp32 accum, cp.async double buffer.
// GATES=1: C0=sigmoid(acc0+b0) (z);  rh=sigmoid(acc1+b1)*H -> Rhi/Rlo[128:256]
// GATES=0: C0=acc0 (y), C1=acc1 (w)
// ---------------------------------------------------------------------------
#define ROWB 80
#define ATILE (128 * ROWB)
#define NARR 6
#define SMEMSZ (2 * NARR * ATILE)     // 122880 B

template <int GATES>
__global__ void __launch_bounds__(512, 1) gemm_dual2(
    const __nv_bfloat16* __restrict__ Ahi, const __nv_bfloat16* __restrict__ Alo,
    const __nv_bfloat16* __restrict__ B0hi, const __nv_bfloat16* __restrict__ B0lo,
    const __nv_bfloat16* __restrict__ B1hi, const __nv_bfloat16* __restrict__ B1lo,
    const float* __restrict__ bias0, const float* __restrict__ bias1,
    const float* __restrict__ H,
    float* __restrict__ C0, float* __restrict__ C1,
    __nv_bfloat16* __restrict__ Rhi, __nv_bfloat16* __restrict__ Rlo, int M)
{
    extern __shared__ __align__(16) char smem[];
    const uint32_t sb = smem_u32(smem);

    const int t = threadIdx.x;
    const int wid = t >> 5, lane = t & 31;
    const int wm = wid >> 2, wn = wid & 3;      // warp grid 4x4
    const int m0 = blockIdx.x * 128;

    const __nv_bfloat16* arrs[6] = {Ahi, Alo, B0hi, B0lo, B1hi, B1lo};

    float acc[2][2][4][4];                      // [mat][mt][nt][q]
    #pragma unroll
    for (int m = 0; m < 2; ++m)
        #pragma unroll
        for (int mt = 0; mt < 2; ++mt)
            #pragma unroll
            for (int nt = 0; nt < 4; ++nt)
                #pragma unroll
                for (int q = 0; q < 4; ++q) acc[m][mt][nt][q] = 0.f;

    const int sr = t >> 2, sq = t & 3;

    auto stage = [&](int c, int b) {
        uint32_t base = sb + (uint32_t)b * (NARR * ATILE) + sr * ROWB + sq * 16;
        size_t go = (size_t)sr * 256 + c * 32 + sq * 8;
        size_t ga = (size_t)(m0 + sr) * 256 + c * 32 + sq * 8;
        cpa16(base + 0 * ATILE, arrs[0] + ga);
        cpa16(base + 1 * ATILE, arrs[1] + ga);
        #pragma unroll
        for (int j = 0; j < 4; ++j)
            cpa16(base + (2 + j) * ATILE, arrs[2 + j] + go);
    };

    stage(0, 0); cp_commit();
    stage(1, 1); cp_commit();

    const int arow = wm * 32 + (lane & 15);
    // B ldmx4 pair addressing: 16 n-rows x 16 k per LDSM
    const int brow = wn * 32 + (lane & 7) + ((lane >> 4) & 1) * 8;
    const int bksel = ((lane >> 3) & 1) * 16;

    for (int c = 0; c < 8; ++c) {
        if (c < 7) asm volatile("cp.async.wait_group 1;" ::: "memory");
        else       asm volatile("cp.async.wait_group 0;" ::: "memory");
        __syncthreads();
        const uint32_t bufo = sb + (uint32_t)(c & 1) * (NARR * ATILE);
        #pragma unroll
        for (int ks = 0; ks < 2; ++ks) {
            uint32_t ah[2][4], al[2][4];
            const int akb = ks * 32 + (lane >> 4) * 16;
            #pragma unroll
            for (int mt = 0; mt < 2; ++mt) {
                uint32_t ao = (uint32_t)((arow + mt * 16) * ROWB + akb);
                ldmx4(ah[mt], bufo + ao);
                ldmx4(al[mt], bufo + ATILE + ao);
            }
            const int bkb = ks * 32 + bksel;
            #pragma unroll
            for (int ntp = 0; ntp < 2; ++ntp) {
                uint32_t ro = (uint32_t)((brow + ntp * 16) * ROWB + bkb);
                #pragma unroll
                for (int m = 0; m < 2; ++m) {
                    uint32_t bh4[4], bl4[4];
                    ldmx4(bh4, bufo + (uint32_t)(2 + 2 * m) * ATILE + ro);
                    ldmx4(bl4, bufo + (uint32_t)(3 + 2 * m) * ATILE + ro);
                    #pragma unroll
                    for (int half = 0; half < 2; ++half) {
                        int nt = 2 * ntp + half;
                        #pragma unroll
                        for (int mt = 0; mt < 2; ++mt) {
                            mma16816(acc[m][mt][nt], ah[mt], bh4 + 2 * half);
                            mma16816(acc[m][mt][nt], ah[mt], bl4 + 2 * half);
                            mma16816(acc[m][mt][nt], al[mt], bh4 + 2 * half);
                        }
                    }
                }
            }
        }
        if (c < 6) {
            __syncthreads();
            stage(c + 2, c & 1);
            cp_commit();
        }
    }

    // ---- epilogue ----
    const int g = lane >> 2, tig = lane & 3;
    #pragma unroll
    for (int m = 0; m < 2; ++m) {
        const float* bias = m ? bias1 : bias0;
        #pragma unroll
        for (int mt = 0; mt < 2; ++mt) {
            #pragma unroll
            for (int nt = 0; nt < 4; ++nt) {
                int col = wn * 32 + nt * 8 + tig * 2;
                float bx = 0.f, by = 0.f;
                if (GATES) { bx = __ldg(bias + col); by = __ldg(bias + col + 1); }
                #pragma unroll
                for (int s = 0; s < 2; ++s) {
                    int r = m0 + wm * 32 + mt * 16 + g + s * 8;
                    if (r < M) {
                        float v0 = acc[m][mt][nt][2 * s], v1 = acc[m][mt][nt][2 * s + 1];
                        if (GATES == 0) {
                            float* C = m ? C1 : C0;
                            *(float2*)(C + (size_t)r * 128 + col) = make_float2(v0, v1);
                        } else if (m == 0) {
                            v0 = sgm(v0 + bx); v1 = sgm(v1 + by);
                            *(float2*)(C0 + (size_t)r * 128 + col) = make_float2(v0, v1);
                        } else {
                            const float2 hv = *(const float2*)(H + (size_t)r * 128 + col);
                            float r0 = sgm(v0 + bx) * hv.x;
                            float r1 = sgm(v1 + by) * hv.y;
                            float h0 = __bfloat162float(__float2bfloat16_rn(r0));
                            float h1 = __bfloat162float(__float2bfloat16_rn(r1));
                            size_t doo = (size_t)r * 256 + 128 + col;
                            *(uint32_t*)(Rhi + doo) = packbf2(r0, r1);
                            *(uint32_t*)(Rlo + doo) = packbf2(r0 - h0, r1 - h1);
                        }
                    }
                }
            }
        }
    }
}

// ---------------------------------------------------------------------------
// CSR build + gather (replaces atomic scatter)
// ---------------------------------------------------------------------------
__global__ void __launch_bounds__(256) hist_kernel(
    const int* __restrict__ ei, int* __restrict__ cnt, int E)
{
    int i = blockIdx.x * 256 + threadIdx.x;
    if (i < E) atomicAdd(cnt + __ldg(ei + E + i), 1);
}

__global__ void __launch_bounds__(256) scan1_kernel(
    const int* __restrict__ deg, int* __restrict__ off, int* __restrict__ bsum, int M)
{
    __shared__ int s[256];
    int tid = threadIdx.x;
    int i = blockIdx.x * 256 + tid;
    int v = (i < M) ? deg[i] : 0;
    s[tid] = v;
    __syncthreads();
    #pragma unroll
    for (int d = 1; d < 256; d <<= 1) {
        int tv = (tid >= d) ? s[tid - d] : 0;
        __syncthreads();
        s[tid] += tv;
        __syncthreads();
    }
    if (i < M) off[i] = s[tid] - v;      // exclusive within block
    if (tid == 255) bsum[blockIdx.x] = s[255];
}

__global__ void __launch_bounds__(256) scan2_kernel(int* __restrict__ bsum, int G)
{
    __shared__ int s[256];
    int tid = threadIdx.x;
    int v = (tid < G) ? bsum[tid] : 0;
    s[tid] = v;
    __syncthreads();
    #pragma unroll
    for (int d = 1; d < 256; d <<= 1) {
        int tv = (tid >= d) ? s[tid - d] : 0;
        __syncthreads();
        s[tid] += tv;
        __syncthreads();
    }
    if (tid < G) bsum[tid] = s[tid] - v;  // exclusive
}

__global__ void __launch_bounds__(256) scan3_kernel(
    int* __restrict__ off, const int* __restrict__ bsum, int M)
{
    int i = blockIdx.x * 256 + threadIdx.x;
    if (i < M) off[i] += bsum[i >> 8];
}

__global__ void __launch_bounds__(256) fill_kernel(
    const int* __restrict__ ei, const int* __restrict__ off,
    int* __restrict__ pos, int* __restrict__ ebuf, int E)
{
    int i = blockIdx.x * 256 + threadIdx.x;
    if (i >= E) return;
    int dst = __ldg(ei + E + i);
    int slot = atomicAdd(pos + dst, 1);
    ebuf[__ldg(off + dst) + slot] = __ldg(ei + i);
}

// One warp per node: sum y over CSR neighbor list. Plain stores to agg.
__global__ void __launch_bounds__(256) gather_kernel(
    const int* __restrict__ off, const int* __restrict__ cnt,
    const int* __restrict__ ebuf, const float* __restrict__ y,
    float* __restrict__ agg, int M)
{
    int n = (int)((blockIdx.x * 256u + threadIdx.x) >> 5);
    int lane = threadIdx.x & 31;
    if (n >= M) return;
    int start = __ldg(off + n);
    int d = __ldg(cnt + n);
    float4 a = make_float4(0.f, 0.f, 0.f, 0.f);
    int j = 0;
    for (; j + 2 <= d; j += 2) {
        int s0 = __ldg(ebuf + start + j);
        int s1 = __ldg(ebuf + start + j + 1);
        float4 v0 = *(const float4*)(y + (size_t)s0 * 128 + lane * 4);
        float4 v1 = *(const float4*)(y + (size_t)s1 * 128 + lane * 4);
        a.x += v0.x + v1.x; a.y += v0.y + v1.y;
        a.z += v0.z + v1.z; a.w += v0.w + v1.w;
    }
    if (j < d) {
        int s0 = __ldg(ebuf + start + j);
        float4 v0 = *(const float4*)(y + (size_t)s0 * 128 + lane * 4);
        a.x += v0.x; a.y += v0.y; a.z += v0.z; a.w += v0.w;
    }
    *(float4*)(agg + (size_t)n * 128 + lane * 4) = a;
}

// out = (1-z) * (agg/max(cnt,1) + b_l + w) + z * h
__global__ void __launch_bounds__(256) final_kernel(
    const float* __restrict__ z, const float* __restrict__ w,
    const float* __restrict__ agg, const int* __restrict__ cnt,
    const float* __restrict__ b_l, const float* __restrict__ h,
    float* __restrict__ out, int M)
{
    int i4 = blockIdx.x * 256 + threadIdx.x;
    if (i4 >= M * 32) return;
    int node = i4 >> 5;
    int c4 = i4 & 31;
    float inv = 1.f / fmaxf((float)__ldg(cnt + node), 1.f);
    size_t off = (size_t)i4 * 4;
    float4 zv = *(const float4*)(z + off);
    float4 wv = *(const float4*)(w + off);
    float4 av = *(const float4*)(agg + off);
    float4 hv = *(const float4*)(h + off);
    float4 bv = *(const float4*)(b_l + c4 * 4);
    float4 o;
    o.x = (1.f - zv.x) * (av.x * inv + bv.x + wv.x) + zv.x * hv.x;
    o.y = (1.f - zv.y) * (av.y * inv + bv.y + wv.y) + zv.y * hv.y;
    o.z = (1.f - zv.z) * (av.z * inv + bv.z + wv.z) + zv.z * hv.z;
    o.w = (1.f - zv.w) * (av.w * inv + bv.w + wv.w) + zv.w * hv.w;
    *(float4*)(out + off) = o;
}

extern "C" void kernel_launch(void* const* d_in, const int* in_sizes, int n_in,
                              void* d_out, int out_size)
{
    const float* x    = (const float*)d_in[0];
    const int*   ei   = (const int*)d_in[1];
    const float* h    = (const float*)d_in[2];
    const float* W_xr = (const float*)d_in[3];
    const float* b_xr = (const float*)d_in[4];
    const float* W_hr = (const float*)d_in[5];
    const float* W_xz = (const float*)d_in[6];
    const float* b_xz = (const float*)d_in[7];
    const float* W_hz = (const float*)d_in[8];
    const float* W_l  = (const float*)d_in[9];
    const float* b_l  = (const float*)d_in[10];
    const float* W_r  = (const float*)d_in[11];
    float* out = (float*)d_out;

    const int M = in_sizes[0] / 128;
    const int E = in_sizes[1] / 2;
    const size_t ND = (size_t)M * 128;

    void* ps = nullptr; cudaGetSymbolAddress(&ps, g_scratch);
    void* pc = nullptr; cudaGetSymbolAddress(&pc, g_cnt);
    void* po = nullptr; cudaGetSymbolAddress(&po, g_off);
    void* pp = nullptr; cudaGetSymbolAddress(&pp, g_pos);
    void* pe = nullptr; cudaGetSymbolAddress(&pe, g_ebuf);
    void* pb = nullptr; cudaGetSymbolAddress(&pb, g_bsum);
    void* pw = nullptr; cudaGetSymbolAddress(&pw, g_wbuf);
    void* pa = nullptr; cudaGetSymbolAddress(&pa, g_abuf);
    float* z   = (float*)ps;
    float* y   = z + ND;
    float* w   = y + ND;
    float* agg = w + ND;
    int* cnt  = (int*)pc;
    int* off  = (int*)po;
    int* pos  = (int*)pp;
    int* ebuf = (int*)pe;
    int* bsum = (int*)pb;
    __nv_bfloat16* wbuf = (__nv_bfloat16*)pw;
    __nv_bfloat16* a1hi = (__nv_bfloat16*)pa;
    __nv_bfloat16* a1lo = a1hi + (size_t)NMAX * 256;
    __nv_bfloat16* a2hi = a1lo + (size_t)NMAX * 256;
    __nv_bfloat16* a2lo = a2hi + (size_t)NMAX * 256;

    cudaFuncSetAttribute(gemm_dual2<0>, cudaFuncAttributeMaxDynamicSharedMemorySize, SMEMSZ);
    cudaFuncSetAttribute(gemm_dual2<1>, cudaFuncAttributeMaxDynamicSharedMemorySize, SMEMSZ);

    cudaMemsetAsync(cnt, 0, M * sizeof(int), 0);
    cudaMemsetAsync(pos, 0, M * sizeof(int), 0);

    // CSR build (depends only on edge_index)
    hist_kernel<<<(E + 255) / 256, 256>>>(ei, cnt, E);
    int G = (M + 255) / 256;
    scan1_kernel<<<G, 256>>>(cnt, off, bsum, M);
    scan2_kernel<<<1, 256>>>(bsum, G);
    scan3_kernel<<<G, 256>>>(off, bsum, M);
    fill_kernel<<<(E + 255) / 256, 256>>>(ei, off, pos, ebuf, E);

    // Prep: weights + A operands
    prep_w<<<512, 256>>>(W_xz, W_hz, W_xr, W_hr, W_l, W_r, wbuf);
    prep_a<<<(M * 32 + 255) / 256, 256>>>(x, h, a1hi, a1lo, a2hi, a2lo, M);

    __nv_bfloat16* BZ_hi = wbuf;
    __nv_bfloat16* BZ_lo = wbuf + 1 * 32768;
    __nv_bfloat16* BR_hi = wbuf + 2 * 32768;
    __nv_bfloat16* BR_lo = wbuf + 3 * 32768;
    __nv_bfloat16* BL_hi = wbuf + 4 * 32768;
    __nv_bfloat16* BL_lo = wbuf + 5 * 32768;
    __nv_bfloat16* BW_hi = wbuf + 6 * 32768;
    __nv_bfloat16* BW_lo = wbuf + 7 * 32768;

    int gb = (M + 127) / 128;
    // z = sigmoid([x|h]@Wz + b_xz) ; rh(bf16 split) = sigmoid([x|h]@Wr + b_xr)*h
    gemm_dual2<1><<<gb, 512, SMEMSZ>>>(a1hi, a1lo, BZ_hi, BZ_lo, BR_hi, BR_lo,
                                       b_xz, b_xr, h, z, nullptr, a2hi, a2lo, M);
    // y = [x|rh]@W_l ; w = [x|rh]@W_r
    gemm_dual2<0><<<gb, 512, SMEMSZ>>>(a2hi, a2lo, BL_hi, BL_lo, BW_hi, BW_lo,
                                       nullptr, nullptr, nullptr, y, w, nullptr, nullptr, M);

    // Mean-neighbor aggregation: CSR gather (no atomics on the feature rows)
    gather_kernel<<<(M * 32 + 255) / 256, 256>>>(off, cnt, ebuf, y, agg, M);

    final_kernel<<<(M * 32 + 255) / 256, 256>>>(z, w, agg, cnt, b_l, h, out, M);
}